// round 5
// baseline (speedup 1.0000x reference)
#include <cuda_runtime.h>
#include <math.h>
#include <cstddef>

// ---------------------------------------------------------------------------
// 3-layer bidirectional GRU, fp32, packed f32x2 FMA (FFMA2).
//   T=256, B=64, IN=2048 (=2H), H=1024, L=3, D=2
// Per layer:
//   0) init_hT  : transpose h0 -> hbufT (once)
//   1) gemm_gx  : gx[T*B,6144] = in @ w_ih^T + b_ih    (both dirs fused)
//   2) 256 x gru_step : fused recurrent GEMM + gates, both dirs.
// gru_step R3: 384 thr, 4-way K-split, 8x4 f32x2 microtile, transposed h.
// ---------------------------------------------------------------------------

#define T_STEPS 256
#define BATCH   64
#define HID     1024
#define GATES   3072     // 3*HID
#define NW      6144     // 2*GATES (both directions)
#define KW      2048     // input width (== 2H for layers 1,2)
#define MW      16384    // T*B

// Scratch (device globals; no allocs).
__device__ float g_gx  [(size_t)MW * NW];                 // 402 MB
__device__ float g_bufA[(size_t)T_STEPS * BATCH * 2048];  // 134 MB
__device__ float g_bufB[(size_t)T_STEPS * BATCH * 2048];  // 134 MB
__device__ float g_hbuf[2 * 2 * HID * BATCH];             // [dir][parity][j][b] TRANSPOSED

// ---- packed fp32x2 helpers (sm_100+) --------------------------------------
__device__ __forceinline__ unsigned long long fma2(unsigned long long a,
                                                   unsigned long long b,
                                                   unsigned long long c) {
    unsigned long long d;
    asm("fma.rn.f32x2 %0, %1, %2, %3;" : "=l"(d) : "l"(a), "l"(b), "l"(c));
    return d;
}
__device__ __forceinline__ float2 unpack2(unsigned long long v) {
    float2 f;
    asm("mov.b64 {%0, %1}, %2;" : "=f"(f.x), "=f"(f.y) : "l"(v));
    return f;
}

// ---------------------------------------------------------------------------
// Kernel 0: transpose h0[l] -> hbufT parity-1 slot.  items = 2*H*B = 131072
// ---------------------------------------------------------------------------
__global__ __launch_bounds__(256) void init_hT(const float* __restrict__ h0_l,
                                               float* __restrict__ hbuf)
{
    int idx = blockIdx.x * 256 + threadIdx.x;      // [0, 131072)
    int d = idx >> 16;
    int r = idx & 65535;
    int j = r & (HID - 1);
    int b = r >> 10;
    hbuf[(size_t)(d * 2 + 1) * (HID * BATCH) + j * BATCH + b] =
        h0_l[(size_t)d * (BATCH * HID) + (size_t)b * HID + j];
}

// ---------------------------------------------------------------------------
// Kernel 1: gx GEMM.  C[m,n] = sum_k A[m,k]*W[n,k] + bias[n]
//   128x128x16 tile, 256 threads, 8x8 microtile, FFMA2, register prefetch.
// ---------------------------------------------------------------------------
__global__ __launch_bounds__(256) void gemm_gx(
    const float* __restrict__ A, const float* __restrict__ W,
    const float* __restrict__ bias, float* __restrict__ C)
{
    __shared__ __align__(16) float2 As2[16][128];
    __shared__ __align__(16) float  Bs [16][128];

    const int tid = threadIdx.x;
    const int tx  = tid & 15;
    const int ty  = tid >> 4;
    const int n0  = blockIdx.x * 128;
    const int m0  = blockIdx.y * 128;

    const int r0  = tid >> 2;
    const int kq4 = (tid & 3) * 4;

    const float* Ap0 = A + (size_t)(m0 + r0)      * KW + kq4;
    const float* Ap1 = A + (size_t)(m0 + r0 + 64) * KW + kq4;
    const float* Wp0 = W + (size_t)(n0 + r0)      * KW + kq4;
    const float* Wp1 = W + (size_t)(n0 + r0 + 64) * KW + kq4;

    unsigned long long acc[8][4];
#pragma unroll
    for (int m = 0; m < 8; m++)
#pragma unroll
        for (int q = 0; q < 4; q++) acc[m][q] = 0ULL;

    float4 va0 = *(const float4*)Ap0;
    float4 va1 = *(const float4*)Ap1;
    float4 vw0 = *(const float4*)Wp0;
    float4 vw1 = *(const float4*)Wp1;

    for (int k0 = 0; k0 < KW; k0 += 16) {
        __syncthreads();
        As2[kq4+0][r0]    = make_float2(va0.x, va0.x);
        As2[kq4+1][r0]    = make_float2(va0.y, va0.y);
        As2[kq4+2][r0]    = make_float2(va0.z, va0.z);
        As2[kq4+3][r0]    = make_float2(va0.w, va0.w);
        As2[kq4+0][r0+64] = make_float2(va1.x, va1.x);
        As2[kq4+1][r0+64] = make_float2(va1.y, va1.y);
        As2[kq4+2][r0+64] = make_float2(va1.z, va1.z);
        As2[kq4+3][r0+64] = make_float2(va1.w, va1.w);
        Bs[kq4+0][r0]     = vw0.x;
        Bs[kq4+1][r0]     = vw0.y;
        Bs[kq4+2][r0]     = vw0.z;
        Bs[kq4+3][r0]     = vw0.w;
        Bs[kq4+0][r0+64]  = vw1.x;
        Bs[kq4+1][r0+64]  = vw1.y;
        Bs[kq4+2][r0+64]  = vw1.z;
        Bs[kq4+3][r0+64]  = vw1.w;
        __syncthreads();

        if (k0 + 16 < KW) {
            va0 = *(const float4*)(Ap0 + k0 + 16);
            va1 = *(const float4*)(Ap1 + k0 + 16);
            vw0 = *(const float4*)(Wp0 + k0 + 16);
            vw1 = *(const float4*)(Wp1 + k0 + 16);
        }

#pragma unroll
        for (int k = 0; k < 16; k++) {
            unsigned long long ad[8];
#pragma unroll
            for (int m = 0; m < 8; m++)
                ad[m] = *(const unsigned long long*)&As2[k][ty*8 + m];
            ulonglong2 bA = *(const ulonglong2*)&Bs[k][tx*8];
            ulonglong2 bB = *(const ulonglong2*)&Bs[k][tx*8 + 4];
#pragma unroll
            for (int m = 0; m < 8; m++) {
                acc[m][0] = fma2(ad[m], bA.x, acc[m][0]);
                acc[m][1] = fma2(ad[m], bA.y, acc[m][1]);
                acc[m][2] = fma2(ad[m], bB.x, acc[m][2]);
                acc[m][3] = fma2(ad[m], bB.y, acc[m][3]);
            }
        }
    }

    float bias8[8];
#pragma unroll
    for (int c = 0; c < 8; c++) bias8[c] = bias[n0 + tx*8 + c];

#pragma unroll
    for (int m = 0; m < 8; m++) {
        float* Cp = C + (size_t)(m0 + ty*8 + m) * NW + n0 + tx*8;
        float o[8];
#pragma unroll
        for (int q = 0; q < 4; q++) {
            float2 f = unpack2(acc[m][q]);
            o[2*q]   = f.x + bias8[2*q];
            o[2*q+1] = f.y + bias8[2*q+1];
        }
        *(float4*)(Cp)     = make_float4(o[0], o[1], o[2], o[3]);
        *(float4*)(Cp + 4) = make_float4(o[4], o[5], o[6], o[7]);
    }
}

// ---------------------------------------------------------------------------
// Kernel 2 (R3): one GRU time step, both directions.
//   grid = 128 CTAs: d = bx>>6, jbase = (bx&63)*16
//   tile [64 b x 48 gathered gate-rows x K=1024], BK=64, 384 threads
//   4-way K-split: group g (96 thr) handles k rows [16g,16g+16) per block
//   microtile: 8 batches (4 f32x2 pairs) x 4 dup'd cols -> 16 FFMA2 / 4 LDS.128
//   h state read/written TRANSPOSED [j][b] -> contiguous, vectorized tile load
// ---------------------------------------------------------------------------
#define ST_THREADS 384
#define WS_PITCH   52          // float2 pitch (16B-aligned rows, low conflicts)
#define GH_PITCH   49
#define SM_HS_F4   1024        // 64 k * 16 float4
#define SM_WS_F4   768         // 48 rows * 16 float4

#define HS(k,b)    hs_f[(k)*64 + (b)]
#define WS(k,c)    ws2[(k)*WS_PITCH + (c)]
#define GH(g,b,c)  ghs[((g)*64 + (b))*GH_PITCH + (c)]

__global__ __launch_bounds__(ST_THREADS, 1) void gru_step(
    const float* __restrict__ gx, const float* __restrict__ whh_l,
    const float* __restrict__ bhh_l, float* __restrict__ hbuf,
    float* __restrict__ yout, float* __restrict__ hn_out, int t)
{
    extern __shared__ char smraw[];
    float*  hs_f = (float*)smraw;                          // [64][64]  16384 B
    float2* ws2  = (float2*)(smraw + 16384);               // [64][52]  26624 B
    float*  ghs  = (float*)(smraw + 16384 + 26624);        // [4][64][49] 50176 B

    const int tid = threadIdx.x;
    const int d     = blockIdx.x >> 6;
    const int jbase = (blockIdx.x & 63) << 4;

    // microtile coords
    const int g  = tid / 96;          // K-split group
    const int r  = tid - g * 96;
    const int tx = r % 12;            // col group: 4 cols
    const int ty = r / 12;            // batch group: 8 batches
    const int c0 = tx * 4;
    const int b0 = ty * 8;
    const int ks = g * 16;            // group's k-slice base within block

    const float* whh = whh_l + (size_t)d * GATES * HID;
    const float* bhh = bhh_l + d * GATES;
    const float* h_in  = hbuf + (size_t)(d * 2 + ((t & 1) ^ 1)) * (HID * BATCH);
    float*       h_out = hbuf + (size_t)(d * 2 + (t & 1))       * (HID * BATCH);
    const int tt = d ? (T_STEPS - 1 - t) : t;

    // tile-load mapping
    //   hs: 1024 float4, contiguous copy -> tid, tid+384, (tid+768 if tid<256)
    //   ws: 768 float4 -> i = tid, tid+384 ; rr = i>>4 (gathered row), q = i&15
    const int rr0 = tid >> 4;                 // 0..23
    const int q0  = tid & 15;
    const int rr1 = rr0 + 24;                 // 24..47
    const int wrow0 = ((rr0 >> 4) * HID) + jbase + (rr0 & 15);
    const int wrow1 = ((rr1 >> 4) * HID) + jbase + (rr1 & 15);
    const float* wp0 = whh + (size_t)wrow0 * HID + 4 * q0;
    const float* wp1 = whh + (size_t)wrow1 * HID + 4 * q0;

    unsigned long long acc[4][4];
#pragma unroll
    for (int p = 0; p < 4; p++)
#pragma unroll
        for (int c = 0; c < 4; c++) acc[p][c] = 0ULL;

    // initial global fetch (block 0)
    const float4* hsrc = (const float4*)h_in;
    float4 hv0 = hsrc[tid];
    float4 hv1 = hsrc[tid + 384];
    float4 hv2 = make_float4(0.f,0.f,0.f,0.f);
    if (tid < 256) hv2 = hsrc[tid + 768];
    float4 wv0 = *(const float4*)wp0;
    float4 wv1 = *(const float4*)wp1;

    for (int blk = 0; blk < 16; blk++) {
        __syncthreads();          // previous compute done
        // store h tile (contiguous float4 copy)
        float4* hdst = (float4*)hs_f;
        hdst[tid]       = hv0;
        hdst[tid + 384] = hv1;
        if (tid < 256) hdst[tid + 768] = hv2;
        // store w tile duplicated
        WS(4*q0+0, rr0) = make_float2(wv0.x, wv0.x);
        WS(4*q0+1, rr0) = make_float2(wv0.y, wv0.y);
        WS(4*q0+2, rr0) = make_float2(wv0.z, wv0.z);
        WS(4*q0+3, rr0) = make_float2(wv0.w, wv0.w);
        WS(4*q0+0, rr1) = make_float2(wv1.x, wv1.x);
        WS(4*q0+1, rr1) = make_float2(wv1.y, wv1.y);
        WS(4*q0+2, rr1) = make_float2(wv1.z, wv1.z);
        WS(4*q0+3, rr1) = make_float2(wv1.w, wv1.w);
        __syncthreads();

        if (blk < 15) {           // prefetch next block into registers
            const float4* hn = (const float4*)(h_in + (blk + 1) * 64 * 64);
            hv0 = hn[tid];
            hv1 = hn[tid + 384];
            if (tid < 256) hv2 = hn[tid + 768];
            wv0 = *(const float4*)(wp0 + (blk + 1) * 64);
            wv1 = *(const float4*)(wp1 + (blk + 1) * 64);
        }

        // compute 16 k's of this group's slice, with per-k operand prefetch
        ulonglong2 a0 = *(const ulonglong2*)&HS(ks, b0);
        ulonglong2 a1 = *(const ulonglong2*)&HS(ks, b0 + 4);
        ulonglong2 w0 = *(const ulonglong2*)&WS(ks, c0);
        ulonglong2 w1 = *(const ulonglong2*)&WS(ks, c0 + 2);
#pragma unroll
        for (int kk = 0; kk < 16; kk++) {
            ulonglong2 na0, na1, nw0, nw1;
            if (kk < 15) {
                na0 = *(const ulonglong2*)&HS(ks + kk + 1, b0);
                na1 = *(const ulonglong2*)&HS(ks + kk + 1, b0 + 4);
                nw0 = *(const ulonglong2*)&WS(ks + kk + 1, c0);
                nw1 = *(const ulonglong2*)&WS(ks + kk + 1, c0 + 2);
            }
            acc[0][0] = fma2(a0.x, w0.x, acc[0][0]);
            acc[1][0] = fma2(a0.y, w0.x, acc[1][0]);
            acc[2][0] = fma2(a1.x, w0.x, acc[2][0]);
            acc[3][0] = fma2(a1.y, w0.x, acc[3][0]);
            acc[0][1] = fma2(a0.x, w0.y, acc[0][1]);
            acc[1][1] = fma2(a0.y, w0.y, acc[1][1]);
            acc[2][1] = fma2(a1.x, w0.y, acc[2][1]);
            acc[3][1] = fma2(a1.y, w0.y, acc[3][1]);
            acc[0][2] = fma2(a0.x, w1.x, acc[0][2]);
            acc[1][2] = fma2(a0.y, w1.x, acc[1][2]);
            acc[2][2] = fma2(a1.x, w1.x, acc[2][2]);
            acc[3][2] = fma2(a1.y, w1.x, acc[3][2]);
            acc[0][3] = fma2(a0.x, w1.y, acc[0][3]);
            acc[1][3] = fma2(a0.y, w1.y, acc[1][3]);
            acc[2][3] = fma2(a1.x, w1.y, acc[2][3]);
            acc[3][3] = fma2(a1.y, w1.y, acc[3][3]);
            a0 = na0; a1 = na1; w0 = nw0; w1 = nw1;
        }
    }

    // spill partial sums per group
#pragma unroll
    for (int p = 0; p < 4; p++)
#pragma unroll
        for (int c = 0; c < 4; c++) {
            float2 f = unpack2(acc[p][c]);
            GH(g, b0 + 2*p,     c0 + c) = f.x;
            GH(g, b0 + 2*p + 1, c0 + c) = f.y;
        }
    __syncthreads();

    // fused gate epilogue: 1024 items (64 b x 16 j)
    const float* gxp = gx + (size_t)tt * BATCH * NW + (size_t)d * GATES;
    for (int idx = tid; idx < BATCH * 16; idx += ST_THREADS) {
        int b  = idx >> 4;
        int jj = idx & 15;
        int j  = jbase + jj;
        float gr = GH(0,b,jj)      + GH(1,b,jj)      + GH(2,b,jj)      + GH(3,b,jj);
        float gz = GH(0,b,16+jj)   + GH(1,b,16+jj)   + GH(2,b,16+jj)   + GH(3,b,16+jj);
        float gn = GH(0,b,32+jj)   + GH(1,b,32+jj)   + GH(2,b,32+jj)   + GH(3,b,32+jj);
        const float* gxb = gxp + (size_t)b * NW;
        float rg = 1.f / (1.f + expf(-(gxb[j]          + gr + bhh[j])));
        float zg = 1.f / (1.f + expf(-(gxb[HID + j]    + gz + bhh[HID + j])));
        float ng = tanhf(gxb[2*HID + j] + rg * (gn + bhh[2*HID + j]));
        float hp = h_in[(size_t)j * BATCH + b];        // transposed read
        float h  = ng + zg * (hp - ng);
        h_out[(size_t)j * BATCH + b] = h;              // transposed write
        if (yout)
            yout[((size_t)tt * BATCH + b) * 2048 + (size_t)d * HID + j] = h;
        if (t == T_STEPS - 1)
            hn_out[(size_t)d * (BATCH * HID) + (size_t)b * HID + j] = h;
    }
}

// ---------------------------------------------------------------------------
// Host: per layer: init_hT + gemm_gx + 256 x gru_step. Capture-safe.
// ---------------------------------------------------------------------------
namespace {
struct EagerLoad {
    EagerLoad() {
        void* p;
        cudaGetSymbolAddress(&p, g_gx);
        cudaGetSymbolAddress(&p, g_bufA);
        cudaGetSymbolAddress(&p, g_bufB);
        cudaGetSymbolAddress(&p, g_hbuf);
    }
} s_eager_load;
}

extern "C" void kernel_launch(void* const* d_in, const int* in_sizes, int n_in,
                              void* d_out, int out_size)
{
    const float* x    = (const float*)d_in[0];
    const float* h0   = (const float*)d_in[1];
    const float* w_ih = (const float*)d_in[2];
    const float* w_hh = (const float*)d_in[3];
    const float* b_ih = (const float*)d_in[4];
    const float* b_hh = (const float*)d_in[5];
    float* out = (float*)d_out;
    (void)in_sizes; (void)n_in; (void)out_size;

    float *gx, *bufA, *bufB, *hbuf;
    cudaGetSymbolAddress((void**)&gx,   g_gx);
    cudaGetSymbolAddress((void**)&bufA, g_bufA);
    cudaGetSymbolAddress((void**)&bufB, g_bufB);
    cudaGetSymbolAddress((void**)&hbuf, g_hbuf);

    const int step_smem = 16384 + 26624 + 50176;   // 93184 B
    cudaFuncSetAttribute(gru_step, cudaFuncAttributeMaxDynamicSharedMemorySize,
                         step_smem);

    dim3 ggrid(NW / 128, MW / 128);   // (48, 128)

    for (int l = 0; l < 3; l++) {
        const float* in = (l == 0) ? x : ((l == 1) ? bufA : bufB);
        float* yout     = (l == 0) ? bufA : ((l == 1) ? bufB : nullptr);

        init_hT<<<512, 256>>>(h0 + (size_t)l * 2 * BATCH * HID, hbuf);

        gemm_gx<<<ggrid, 256>>>(in, w_ih + (size_t)l * NW * KW,
                                b_ih + (size_t)l * NW, gx);

        for (int t = 0; t < T_STEPS; t++) {
            gru_step<<<128, ST_THREADS, step_smem>>>(
                gx,
                w_hh + (size_t)l * 2 * GATES * HID,
                b_hh + (size_t)l * NW,
                hbuf, yout,
                out + (size_t)l * 2 * BATCH * HID,
                t);
        }
    }
}

// round 6
// speedup vs baseline: 1.0009x; 1.0009x over previous
#include <cuda_runtime.h>
#include <math.h>
#include <cstddef>

// ---------------------------------------------------------------------------
// 3-layer bidirectional GRU, fp32, packed f32x2 FMA (FFMA2).
//   T=256, B=64, IN=2048 (=2H), H=1024, L=3, D=2
// Per layer:
//   0) init_hT  : transpose h0 -> hbufT (once)
//   1) gemm_gx  : gx[T*B,6144] = in @ w_ih^T + b_ih    (both dirs fused)
//   2) 256 x gru_step : fused recurrent GEMM + gates, both dirs.
// gru_step R3: 384 thr, 4-way K-split, 8x4 f32x2 microtile, transposed h.
// ---------------------------------------------------------------------------

#define T_STEPS 256
#define BATCH   64
#define HID     1024
#define GATES   3072     // 3*HID
#define NW      6144     // 2*GATES (both directions)
#define KW      2048     // input width (== 2H for layers 1,2)
#define MW      16384    // T*B

// Scratch (device globals; no allocs).
__device__ float g_gx  [(size_t)MW * NW];                 // 402 MB
__device__ float g_bufA[(size_t)T_STEPS * BATCH * 2048];  // 134 MB
__device__ float g_bufB[(size_t)T_STEPS * BATCH * 2048];  // 134 MB
__device__ float g_hbuf[2 * 2 * HID * BATCH];             // [dir][parity][j][b] TRANSPOSED

// ---- packed fp32x2 helpers (sm_100+) --------------------------------------
__device__ __forceinline__ unsigned long long fma2(unsigned long long a,
                                                   unsigned long long b,
                                                   unsigned long long c) {
    unsigned long long d;
    asm("fma.rn.f32x2 %0, %1, %2, %3;" : "=l"(d) : "l"(a), "l"(b), "l"(c));
    return d;
}
__device__ __forceinline__ float2 unpack2(unsigned long long v) {
    float2 f;
    asm("mov.b64 {%0, %1}, %2;" : "=f"(f.x), "=f"(f.y) : "l"(v));
    return f;
}

// ---------------------------------------------------------------------------
// Kernel 0: transpose h0[l] -> hbufT parity-1 slot.  items = 2*H*B = 131072
// ---------------------------------------------------------------------------
__global__ __launch_bounds__(256) void init_hT(const float* __restrict__ h0_l,
                                               float* __restrict__ hbuf)
{
    int idx = blockIdx.x * 256 + threadIdx.x;      // [0, 131072)
    int d = idx >> 16;
    int r = idx & 65535;
    int j = r & (HID - 1);
    int b = r >> 10;
    hbuf[(size_t)(d * 2 + 1) * (HID * BATCH) + j * BATCH + b] =
        h0_l[(size_t)d * (BATCH * HID) + (size_t)b * HID + j];
}

// ---------------------------------------------------------------------------
// Kernel 1: gx GEMM.  C[m,n] = sum_k A[m,k]*W[n,k] + bias[n]
//   128x128x16 tile, 256 threads, 8x8 microtile, FFMA2, register prefetch.
// ---------------------------------------------------------------------------
__global__ __launch_bounds__(256) void gemm_gx(
    const float* __restrict__ A, const float* __restrict__ W,
    const float* __restrict__ bias, float* __restrict__ C)
{
    __shared__ __align__(16) float2 As2[16][128];
    __shared__ __align__(16) float  Bs [16][128];

    const int tid = threadIdx.x;
    const int tx  = tid & 15;
    const int ty  = tid >> 4;
    const int n0  = blockIdx.x * 128;
    const int m0  = blockIdx.y * 128;

    const int r0  = tid >> 2;
    const int kq4 = (tid & 3) * 4;

    const float* Ap0 = A + (size_t)(m0 + r0)      * KW + kq4;
    const float* Ap1 = A + (size_t)(m0 + r0 + 64) * KW + kq4;
    const float* Wp0 = W + (size_t)(n0 + r0)      * KW + kq4;
    const float* Wp1 = W + (size_t)(n0 + r0 + 64) * KW + kq4;

    unsigned long long acc[8][4];
#pragma unroll
    for (int m = 0; m < 8; m++)
#pragma unroll
        for (int q = 0; q < 4; q++) acc[m][q] = 0ULL;

    float4 va0 = *(const float4*)Ap0;
    float4 va1 = *(const float4*)Ap1;
    float4 vw0 = *(const float4*)Wp0;
    float4 vw1 = *(const float4*)Wp1;

    for (int k0 = 0; k0 < KW; k0 += 16) {
        __syncthreads();
        As2[kq4+0][r0]    = make_float2(va0.x, va0.x);
        As2[kq4+1][r0]    = make_float2(va0.y, va0.y);
        As2[kq4+2][r0]    = make_float2(va0.z, va0.z);
        As2[kq4+3][r0]    = make_float2(va0.w, va0.w);
        As2[kq4+0][r0+64] = make_float2(va1.x, va1.x);
        As2[kq4+1][r0+64] = make_float2(va1.y, va1.y);
        As2[kq4+2][r0+64] = make_float2(va1.z, va1.z);
        As2[kq4+3][r0+64] = make_float2(va1.w, va1.w);
        Bs[kq4+0][r0]     = vw0.x;
        Bs[kq4+1][r0]     = vw0.y;
        Bs[kq4+2][r0]     = vw0.z;
        Bs[kq4+3][r0]     = vw0.w;
        Bs[kq4+0][r0+64]  = vw1.x;
        Bs[kq4+1][r0+64]  = vw1.y;
        Bs[kq4+2][r0+64]  = vw1.z;
        Bs[kq4+3][r0+64]  = vw1.w;
        __syncthreads();

        if (k0 + 16 < KW) {
            va0 = *(const float4*)(Ap0 + k0 + 16);
            va1 = *(const float4*)(Ap1 + k0 + 16);
            vw0 = *(const float4*)(Wp0 + k0 + 16);
            vw1 = *(const float4*)(Wp1 + k0 + 16);
        }

#pragma unroll
        for (int k = 0; k < 16; k++) {
            unsigned long long ad[8];
#pragma unroll
            for (int m = 0; m < 8; m++)
                ad[m] = *(const unsigned long long*)&As2[k][ty*8 + m];
            ulonglong2 bA = *(const ulonglong2*)&Bs[k][tx*8];
            ulonglong2 bB = *(const ulonglong2*)&Bs[k][tx*8 + 4];
#pragma unroll
            for (int m = 0; m < 8; m++) {
                acc[m][0] = fma2(ad[m], bA.x, acc[m][0]);
                acc[m][1] = fma2(ad[m], bA.y, acc[m][1]);
                acc[m][2] = fma2(ad[m], bB.x, acc[m][2]);
                acc[m][3] = fma2(ad[m], bB.y, acc[m][3]);
            }
        }
    }

    float bias8[8];
#pragma unroll
    for (int c = 0; c < 8; c++) bias8[c] = bias[n0 + tx*8 + c];

#pragma unroll
    for (int m = 0; m < 8; m++) {
        float* Cp = C + (size_t)(m0 + ty*8 + m) * NW + n0 + tx*8;
        float o[8];
#pragma unroll
        for (int q = 0; q < 4; q++) {
            float2 f = unpack2(acc[m][q]);
            o[2*q]   = f.x + bias8[2*q];
            o[2*q+1] = f.y + bias8[2*q+1];
        }
        *(float4*)(Cp)     = make_float4(o[0], o[1], o[2], o[3]);
        *(float4*)(Cp + 4) = make_float4(o[4], o[5], o[6], o[7]);
    }
}

// ---------------------------------------------------------------------------
// Kernel 2 (R3): one GRU time step, both directions.
//   grid = 128 CTAs: d = bx>>6, jbase = (bx&63)*16
//   tile [64 b x 48 gathered gate-rows x K=1024], BK=64, 384 threads
//   4-way K-split: group g (96 thr) handles k rows [16g,16g+16) per block
//   microtile: 8 batches (4 f32x2 pairs) x 4 dup'd cols -> 16 FFMA2 / 4 LDS.128
//   h state read/written TRANSPOSED [j][b] -> contiguous, vectorized tile load
// ---------------------------------------------------------------------------
#define ST_THREADS 384
#define WS_PITCH   52          // float2 pitch (16B-aligned rows, low conflicts)
#define GH_PITCH   49
#define SM_HS_F4   1024        // 64 k * 16 float4
#define SM_WS_F4   768         // 48 rows * 16 float4

#define HS(k,b)    hs_f[(k)*64 + (b)]
#define WS(k,c)    ws2[(k)*WS_PITCH + (c)]
#define GH(g,b,c)  ghs[((g)*64 + (b))*GH_PITCH + (c)]

__global__ __launch_bounds__(ST_THREADS, 1) void gru_step(
    const float* __restrict__ gx, const float* __restrict__ whh_l,
    const float* __restrict__ bhh_l, float* __restrict__ hbuf,
    float* __restrict__ yout, float* __restrict__ hn_out, int t)
{
    extern __shared__ char smraw[];
    float*  hs_f = (float*)smraw;                          // [64][64]  16384 B
    float2* ws2  = (float2*)(smraw + 16384);               // [64][52]  26624 B
    float*  ghs  = (float*)(smraw + 16384 + 26624);        // [4][64][49] 50176 B

    const int tid = threadIdx.x;
    const int d     = blockIdx.x >> 6;
    const int jbase = (blockIdx.x & 63) << 4;

    // microtile coords
    const int g  = tid / 96;          // K-split group
    const int r  = tid - g * 96;
    const int tx = r % 12;            // col group: 4 cols
    const int ty = r / 12;            // batch group: 8 batches
    const int c0 = tx * 4;
    const int b0 = ty * 8;
    const int ks = g * 16;            // group's k-slice base within block

    const float* whh = whh_l + (size_t)d * GATES * HID;
    const float* bhh = bhh_l + d * GATES;
    const float* h_in  = hbuf + (size_t)(d * 2 + ((t & 1) ^ 1)) * (HID * BATCH);
    float*       h_out = hbuf + (size_t)(d * 2 + (t & 1))       * (HID * BATCH);
    const int tt = d ? (T_STEPS - 1 - t) : t;

    // tile-load mapping
    //   hs: 1024 float4, contiguous copy -> tid, tid+384, (tid+768 if tid<256)
    //   ws: 768 float4 -> i = tid, tid+384 ; rr = i>>4 (gathered row), q = i&15
    const int rr0 = tid >> 4;                 // 0..23
    const int q0  = tid & 15;
    const int rr1 = rr0 + 24;                 // 24..47
    const int wrow0 = ((rr0 >> 4) * HID) + jbase + (rr0 & 15);
    const int wrow1 = ((rr1 >> 4) * HID) + jbase + (rr1 & 15);
    const float* wp0 = whh + (size_t)wrow0 * HID + 4 * q0;
    const float* wp1 = whh + (size_t)wrow1 * HID + 4 * q0;

    unsigned long long acc[4][4];
#pragma unroll
    for (int p = 0; p < 4; p++)
#pragma unroll
        for (int c = 0; c < 4; c++) acc[p][c] = 0ULL;

    // initial global fetch (block 0)
    const float4* hsrc = (const float4*)h_in;
    float4 hv0 = hsrc[tid];
    float4 hv1 = hsrc[tid + 384];
    float4 hv2 = make_float4(0.f,0.f,0.f,0.f);
    if (tid < 256) hv2 = hsrc[tid + 768];
    float4 wv0 = *(const float4*)wp0;
    float4 wv1 = *(const float4*)wp1;

    for (int blk = 0; blk < 16; blk++) {
        __syncthreads();          // previous compute done
        // store h tile (contiguous float4 copy)
        float4* hdst = (float4*)hs_f;
        hdst[tid]       = hv0;
        hdst[tid + 384] = hv1;
        if (tid < 256) hdst[tid + 768] = hv2;
        // store w tile duplicated
        WS(4*q0+0, rr0) = make_float2(wv0.x, wv0.x);
        WS(4*q0+1, rr0) = make_float2(wv0.y, wv0.y);
        WS(4*q0+2, rr0) = make_float2(wv0.z, wv0.z);
        WS(4*q0+3, rr0) = make_float2(wv0.w, wv0.w);
        WS(4*q0+0, rr1) = make_float2(wv1.x, wv1.x);
        WS(4*q0+1, rr1) = make_float2(wv1.y, wv1.y);
        WS(4*q0+2, rr1) = make_float2(wv1.z, wv1.z);
        WS(4*q0+3, rr1) = make_float2(wv1.w, wv1.w);
        __syncthreads();

        if (blk < 15) {           // prefetch next block into registers
            const float4* hn = (const float4*)(h_in + (blk + 1) * 64 * 64);
            hv0 = hn[tid];
            hv1 = hn[tid + 384];
            if (tid < 256) hv2 = hn[tid + 768];
            wv0 = *(const float4*)(wp0 + (blk + 1) * 64);
            wv1 = *(const float4*)(wp1 + (blk + 1) * 64);
        }

        // compute 16 k's of this group's slice, with per-k operand prefetch
        ulonglong2 a0 = *(const ulonglong2*)&HS(ks, b0);
        ulonglong2 a1 = *(const ulonglong2*)&HS(ks, b0 + 4);
        ulonglong2 w0 = *(const ulonglong2*)&WS(ks, c0);
        ulonglong2 w1 = *(const ulonglong2*)&WS(ks, c0 + 2);
#pragma unroll
        for (int kk = 0; kk < 16; kk++) {
            ulonglong2 na0, na1, nw0, nw1;
            if (kk < 15) {
                na0 = *(const ulonglong2*)&HS(ks + kk + 1, b0);
                na1 = *(const ulonglong2*)&HS(ks + kk + 1, b0 + 4);
                nw0 = *(const ulonglong2*)&WS(ks + kk + 1, c0);
                nw1 = *(const ulonglong2*)&WS(ks + kk + 1, c0 + 2);
            }
            acc[0][0] = fma2(a0.x, w0.x, acc[0][0]);
            acc[1][0] = fma2(a0.y, w0.x, acc[1][0]);
            acc[2][0] = fma2(a1.x, w0.x, acc[2][0]);
            acc[3][0] = fma2(a1.y, w0.x, acc[3][0]);
            acc[0][1] = fma2(a0.x, w0.y, acc[0][1]);
            acc[1][1] = fma2(a0.y, w0.y, acc[1][1]);
            acc[2][1] = fma2(a1.x, w0.y, acc[2][1]);
            acc[3][1] = fma2(a1.y, w0.y, acc[3][1]);
            acc[0][2] = fma2(a0.x, w1.x, acc[0][2]);
            acc[1][2] = fma2(a0.y, w1.x, acc[1][2]);
            acc[2][2] = fma2(a1.x, w1.x, acc[2][2]);
            acc[3][2] = fma2(a1.y, w1.x, acc[3][2]);
            acc[0][3] = fma2(a0.x, w1.y, acc[0][3]);
            acc[1][3] = fma2(a0.y, w1.y, acc[1][3]);
            acc[2][3] = fma2(a1.x, w1.y, acc[2][3]);
            acc[3][3] = fma2(a1.y, w1.y, acc[3][3]);
            a0 = na0; a1 = na1; w0 = nw0; w1 = nw1;
        }
    }

    // spill partial sums per group
#pragma unroll
    for (int p = 0; p < 4; p++)
#pragma unroll
        for (int c = 0; c < 4; c++) {
            float2 f = unpack2(acc[p][c]);
            GH(g, b0 + 2*p,     c0 + c) = f.x;
            GH(g, b0 + 2*p + 1, c0 + c) = f.y;
        }
    __syncthreads();

    // fused gate epilogue: 1024 items (64 b x 16 j)
    const float* gxp = gx + (size_t)tt * BATCH * NW + (size_t)d * GATES;
    for (int idx = tid; idx < BATCH * 16; idx += ST_THREADS) {
        int b  = idx >> 4;
        int jj = idx & 15;
        int j  = jbase + jj;
        float gr = GH(0,b,jj)      + GH(1,b,jj)      + GH(2,b,jj)      + GH(3,b,jj);
        float gz = GH(0,b,16+jj)   + GH(1,b,16+jj)   + GH(2,b,16+jj)   + GH(3,b,16+jj);
        float gn = GH(0,b,32+jj)   + GH(1,b,32+jj)   + GH(2,b,32+jj)   + GH(3,b,32+jj);
        const float* gxb = gxp + (size_t)b * NW;
        float rg = 1.f / (1.f + expf(-(gxb[j]          + gr + bhh[j])));
        float zg = 1.f / (1.f + expf(-(gxb[HID + j]    + gz + bhh[HID + j])));
        float ng = tanhf(gxb[2*HID + j] + rg * (gn + bhh[2*HID + j]));
        float hp = h_in[(size_t)j * BATCH + b];        // transposed read
        float h  = ng + zg * (hp - ng);
        h_out[(size_t)j * BATCH + b] = h;              // transposed write
        if (yout)
            yout[((size_t)tt * BATCH + b) * 2048 + (size_t)d * HID + j] = h;
        if (t == T_STEPS - 1)
            hn_out[(size_t)d * (BATCH * HID) + (size_t)b * HID + j] = h;
    }
}

// ---------------------------------------------------------------------------
// Host: per layer: init_hT + gemm_gx + 256 x gru_step. Capture-safe.
// ---------------------------------------------------------------------------
namespace {
struct EagerLoad {
    EagerLoad() {
        void* p;
        cudaGetSymbolAddress(&p, g_gx);
        cudaGetSymbolAddress(&p, g_bufA);
        cudaGetSymbolAddress(&p, g_bufB);
        cudaGetSymbolAddress(&p, g_hbuf);
    }
} s_eager_load;
}

extern "C" void kernel_launch(void* const* d_in, const int* in_sizes, int n_in,
                              void* d_out, int out_size)
{
    const float* x    = (const float*)d_in[0];
    const float* h0   = (const float*)d_in[1];
    const float* w_ih = (const float*)d_in[2];
    const float* w_hh = (const float*)d_in[3];
    const float* b_ih = (const float*)d_in[4];
    const float* b_hh = (const float*)d_in[5];
    float* out = (float*)d_out;
    (void)in_sizes; (void)n_in; (void)out_size;

    float *gx, *bufA, *bufB, *hbuf;
    cudaGetSymbolAddress((void**)&gx,   g_gx);
    cudaGetSymbolAddress((void**)&bufA, g_bufA);
    cudaGetSymbolAddress((void**)&bufB, g_bufB);
    cudaGetSymbolAddress((void**)&hbuf, g_hbuf);

    const int step_smem = 16384 + 26624 + 50176;   // 93184 B
    cudaFuncSetAttribute(gru_step, cudaFuncAttributeMaxDynamicSharedMemorySize,
                         step_smem);

    dim3 ggrid(NW / 128, MW / 128);   // (48, 128)

    for (int l = 0; l < 3; l++) {
        const float* in = (l == 0) ? x : ((l == 1) ? bufA : bufB);
        float* yout     = (l == 0) ? bufA : ((l == 1) ? bufB : nullptr);

        init_hT<<<512, 256>>>(h0 + (size_t)l * 2 * BATCH * HID, hbuf);

        gemm_gx<<<ggrid, 256>>>(in, w_ih + (size_t)l * NW * KW,
                                b_ih + (size_t)l * NW, gx);

        for (int t = 0; t < T_STEPS; t++) {
            gru_step<<<128, ST_THREADS, step_smem>>>(
                gx,
                w_hh + (size_t)l * 2 * GATES * HID,
                b_hh + (size_t)l * NW,
                hbuf, yout,
                out + (size_t)l * 2 * BATCH * HID,
                t);
        }
    }
}

// round 7
// speedup vs baseline: 1.3753x; 1.3740x over previous
#include <cuda_runtime.h>
#include <math.h>
#include <cstddef>

// ---------------------------------------------------------------------------
// 3-layer bidirectional GRU, fp32, FFMA2 (fma.rn.f32x2).
//   T=256, B=64, IN=2048 (=2H), H=1024, L=3, D=2
// Per layer:
//   0) init_layer : transpose h0 -> hbufT parity-1 slot, zero grid barrier
//   1) gemm_gx    : gx[T*B,6144] = in @ w_ih^T + b_ih     (both dirs fused)
//   2) gru_layer  : ONE PERSISTENT KERNEL runs all 256 steps.
//        - whh slice (48 x 1024 = 192 KB) resident in SMEM the whole layer
//        - gmem spin barrier between steps (128 CTAs = 1 wave, co-resident)
// ---------------------------------------------------------------------------

#define T_STEPS 256
#define BATCH   64
#define HID     1024
#define GATES   3072
#define NW      6144
#define KW      2048
#define MW      16384

#define LT_THREADS 384
#define BK      32
#define WPITCH  50            // floats per k-row of wsT (even, conflict-free)

__device__ float g_gx  [(size_t)MW * NW];
__device__ float g_bufA[(size_t)T_STEPS * BATCH * 2048];
__device__ float g_bufB[(size_t)T_STEPS * BATCH * 2048];
__device__ float g_hbuf[2 * 2 * HID * BATCH];   // [dir][parity][j][b] transposed
__device__ unsigned g_bar;                      // grid barrier counter

typedef unsigned long long ull;

__device__ __forceinline__ ull fma2(ull a, ull b, ull c) {
    ull d;
    asm("fma.rn.f32x2 %0, %1, %2, %3;" : "=l"(d) : "l"(a), "l"(b), "l"(c));
    return d;
}
__device__ __forceinline__ ull add2(ull a, ull b) {
    ull d;
    asm("add.rn.f32x2 %0, %1, %2;" : "=l"(d) : "l"(a), "l"(b));
    return d;
}
__device__ __forceinline__ float2 unpack2(ull v) {
    float2 f;
    asm("mov.b64 {%0, %1}, %2;" : "=f"(f.x), "=f"(f.y) : "l"(v));
    return f;
}
__device__ __forceinline__ float4 ldcg4(const float4* p) {
    float4 v;
    asm volatile("ld.global.cg.v4.f32 {%0,%1,%2,%3}, [%4];"
                 : "=f"(v.x), "=f"(v.y), "=f"(v.z), "=f"(v.w) : "l"(p));
    return v;
}
__device__ __forceinline__ float ldcg1(const float* p) {
    float v;
    asm volatile("ld.global.cg.f32 %0, [%1];" : "=f"(v) : "l"(p));
    return v;
}

// ---------------------------------------------------------------------------
// Kernel 0: per-layer init. Transpose h0[l] -> hbufT parity-1; zero g_bar.
// ---------------------------------------------------------------------------
__global__ __launch_bounds__(256) void init_layer(const float* __restrict__ h0_l,
                                                  float* __restrict__ hbuf)
{
    int idx = blockIdx.x * 256 + threadIdx.x;      // [0, 131072)
    if (idx == 0) g_bar = 0u;
    int d = idx >> 16;
    int r = idx & 65535;
    int j = r & (HID - 1);
    int b = r >> 10;
    hbuf[(size_t)(d * 2 + 1) * (HID * BATCH) + j * BATCH + b] =
        h0_l[(size_t)d * (BATCH * HID) + (size_t)b * HID + j];
}

// ---------------------------------------------------------------------------
// Kernel 1: gx GEMM (near FFMA2 roofline; unchanged).
// ---------------------------------------------------------------------------
__global__ __launch_bounds__(256) void gemm_gx(
    const float* __restrict__ A, const float* __restrict__ W,
    const float* __restrict__ bias, float* __restrict__ C)
{
    __shared__ __align__(16) float2 As2[16][128];
    __shared__ __align__(16) float  Bs [16][128];

    const int tid = threadIdx.x;
    const int tx  = tid & 15;
    const int ty  = tid >> 4;
    const int n0  = blockIdx.x * 128;
    const int m0  = blockIdx.y * 128;

    const int r0  = tid >> 2;
    const int kq4 = (tid & 3) * 4;

    const float* Ap0 = A + (size_t)(m0 + r0)      * KW + kq4;
    const float* Ap1 = A + (size_t)(m0 + r0 + 64) * KW + kq4;
    const float* Wp0 = W + (size_t)(n0 + r0)      * KW + kq4;
    const float* Wp1 = W + (size_t)(n0 + r0 + 64) * KW + kq4;

    ull acc[8][4];
#pragma unroll
    for (int m = 0; m < 8; m++)
#pragma unroll
        for (int q = 0; q < 4; q++) acc[m][q] = 0ULL;

    float4 va0 = *(const float4*)Ap0;
    float4 va1 = *(const float4*)Ap1;
    float4 vw0 = *(const float4*)Wp0;
    float4 vw1 = *(const float4*)Wp1;

    for (int k0 = 0; k0 < KW; k0 += 16) {
        __syncthreads();
        As2[kq4+0][r0]    = make_float2(va0.x, va0.x);
        As2[kq4+1][r0]    = make_float2(va0.y, va0.y);
        As2[kq4+2][r0]    = make_float2(va0.z, va0.z);
        As2[kq4+3][r0]    = make_float2(va0.w, va0.w);
        As2[kq4+0][r0+64] = make_float2(va1.x, va1.x);
        As2[kq4+1][r0+64] = make_float2(va1.y, va1.y);
        As2[kq4+2][r0+64] = make_float2(va1.z, va1.z);
        As2[kq4+3][r0+64] = make_float2(va1.w, va1.w);
        Bs[kq4+0][r0]     = vw0.x;
        Bs[kq4+1][r0]     = vw0.y;
        Bs[kq4+2][r0]     = vw0.z;
        Bs[kq4+3][r0]     = vw0.w;
        Bs[kq4+0][r0+64]  = vw1.x;
        Bs[kq4+1][r0+64]  = vw1.y;
        Bs[kq4+2][r0+64]  = vw1.z;
        Bs[kq4+3][r0+64]  = vw1.w;
        __syncthreads();

        if (k0 + 16 < KW) {
            va0 = *(const float4*)(Ap0 + k0 + 16);
            va1 = *(const float4*)(Ap1 + k0 + 16);
            vw0 = *(const float4*)(Wp0 + k0 + 16);
            vw1 = *(const float4*)(Wp1 + k0 + 16);
        }

#pragma unroll
        for (int k = 0; k < 16; k++) {
            ull ad[8];
#pragma unroll
            for (int m = 0; m < 8; m++)
                ad[m] = *(const ull*)&As2[k][ty*8 + m];
            ulonglong2 bA = *(const ulonglong2*)&Bs[k][tx*8];
            ulonglong2 bB = *(const ulonglong2*)&Bs[k][tx*8 + 4];
#pragma unroll
            for (int m = 0; m < 8; m++) {
                acc[m][0] = fma2(ad[m], bA.x, acc[m][0]);
                acc[m][1] = fma2(ad[m], bA.y, acc[m][1]);
                acc[m][2] = fma2(ad[m], bB.x, acc[m][2]);
                acc[m][3] = fma2(ad[m], bB.y, acc[m][3]);
            }
        }
    }

    float bias8[8];
#pragma unroll
    for (int c = 0; c < 8; c++) bias8[c] = bias[n0 + tx*8 + c];

#pragma unroll
    for (int m = 0; m < 8; m++) {
        float* Cp = C + (size_t)(m0 + ty*8 + m) * NW + n0 + tx*8;
        float o[8];
#pragma unroll
        for (int q = 0; q < 4; q++) {
            float2 f = unpack2(acc[m][q]);
            o[2*q]   = f.x + bias8[2*q];
            o[2*q+1] = f.y + bias8[2*q+1];
        }
        *(float4*)(Cp)     = make_float4(o[0], o[1], o[2], o[3]);
        *(float4*)(Cp + 4) = make_float4(o[4], o[5], o[6], o[7]);
    }
}

// ---------------------------------------------------------------------------
// Kernel 2: persistent per-layer GRU. 128 CTAs: d = bx>>6, jbase=(bx&63)*16.
// SMEM: wsT[1024][50] (whh slice, [k][c]) + hs2[32][64] float2 (dup'd h;
// overlaid by reduction buffer and gh result) + 48 bias floats.
// ---------------------------------------------------------------------------
#define SM_WS_BYTES  (HID * WPITCH * 4)          // 204800
#define SM_HS_BYTES  (BK * BATCH * 8)            // 16384
#define SM_TOTAL     (SM_WS_BYTES + SM_HS_BYTES + 256)   // 221440

__device__ __forceinline__ void red_write(ull* red, int r, ull acc[2][8]) {
#pragma unroll
    for (int cp = 0; cp < 2; cp++)
#pragma unroll
        for (int bb = 0; bb < 8; bb++)
            red[(cp * 8 + bb) * 96 + r] = acc[cp][bb];
}
__device__ __forceinline__ void red_add(const ull* red, int r, ull acc[2][8]) {
#pragma unroll
    for (int cp = 0; cp < 2; cp++)
#pragma unroll
        for (int bb = 0; bb < 8; bb++)
            acc[cp][bb] = add2(acc[cp][bb], red[(cp * 8 + bb) * 96 + r]);
}

__global__ __launch_bounds__(LT_THREADS, 1) void gru_layer(
    const float* __restrict__ gx, const float* __restrict__ whh_l,
    const float* __restrict__ bhh_l, float* __restrict__ hbuf,
    float* __restrict__ yout, float* __restrict__ hn_out)
{
    extern __shared__ char smraw[];
    float*  wsT = (float*)smraw;                        // [1024][WPITCH]
    float2* hs2 = (float2*)(smraw + SM_WS_BYTES);       // [BK][64] dup'd h
    ull*    red = (ull*)hs2;                            // overlay: reduction
    float*  ghf = (float*)hs2;                          // overlay: gh [64][48]
    float*  bsm = (float*)(smraw + SM_WS_BYTES + SM_HS_BYTES);

    const int tid = threadIdx.x;
    const int d     = blockIdx.x >> 6;
    const int jbase = (blockIdx.x & 63) << 4;
    const int g  = tid / 96;          // K-split group 0..3
    const int r  = tid - g * 96;
    const int tx = r % 12;            // col pairs (2tx,2tx+1) and (24+2tx,..)
    const int ty = r / 12;            // batches b0..b0+7
    const int b0 = ty * 8;

    const float* whh = whh_l + (size_t)d * GATES * HID;
    const float* bhh = bhh_l + d * GATES;

    // ---- load whh slice into wsT ([k][c]) once per layer ----
#pragma unroll 4
    for (int it = 0; it < 32; it++) {
        int f4i = tid + it * 384;            // 0..12287
        int c   = f4i >> 8;                  // 0..47
        int kq  = (f4i & 255) << 2;
        int grow = ((c >> 4) << 10) + jbase + (c & 15);
        float4 v = *(const float4*)(whh + (size_t)grow * HID + kq);
        wsT[(kq + 0) * WPITCH + c] = v.x;
        wsT[(kq + 1) * WPITCH + c] = v.y;
        wsT[(kq + 2) * WPITCH + c] = v.z;
        wsT[(kq + 3) * WPITCH + c] = v.w;
    }
    if (tid < 48)
        bsm[tid] = bhh[((tid >> 4) << 10) + jbase + (tid & 15)];
    __syncthreads();

    for (int t = 0; t < T_STEPS; t++) {
        const float* h_in  = hbuf + (size_t)(d*2 + ((t&1)^1)) * (HID*BATCH);
        float*       h_out = hbuf + (size_t)(d*2 + (t&1))     * (HID*BATCH);
        const int tt = d ? (T_STEPS - 1 - t) : t;
        const float* gxp = gx + (size_t)tt * BATCH * NW + (size_t)d * GATES;

        // prefetch epilogue operands (hidden under the mainloop)
        float pgr[3], pgz[3], pgn[3], php[3];
#pragma unroll
        for (int e = 0; e < 3; e++) {
            int idx = tid + 384 * e;
            pgr[e] = pgz[e] = pgn[e] = php[e] = 0.f;
            if (idx < 1024) {
                int b = idx >> 4, jj = idx & 15, j = jbase + jj;
                const float* gxb = gxp + (size_t)b * NW;
                pgr[e] = __ldg(gxb + j);
                pgz[e] = __ldg(gxb + HID + j);
                pgn[e] = __ldg(gxb + 2*HID + j);
                php[e] = ldcg1(h_in + (size_t)j * BATCH + b);
            }
        }

        ull acc[2][8];
#pragma unroll
        for (int cp = 0; cp < 2; cp++)
#pragma unroll
            for (int bb = 0; bb < 8; bb++) acc[cp][bb] = 0ULL;

        // initial staging fetch (blk 0): 512 float4 per block
        const float4* hsrc = (const float4*)h_in;     // [j][b]
        float4 hv0 = ldcg4(hsrc + tid);
        float4 hv1 = make_float4(0.f,0.f,0.f,0.f);
        if (tid < 128) hv1 = ldcg4(hsrc + 384 + tid);

        for (int blk = 0; blk < HID / BK; blk++) {     // 32 blocks
            __syncthreads();
            {   // store duplicated h tile
                int k  = tid >> 4;
                int b4 = (tid & 15) << 2;
                float4* p = (float4*)&hs2[k * 64 + b4];
                p[0] = make_float4(hv0.x, hv0.x, hv0.y, hv0.y);
                p[1] = make_float4(hv0.z, hv0.z, hv0.w, hv0.w);
                if (tid < 128) {
                    int i1 = 384 + tid;
                    int k1 = i1 >> 4, b41 = (i1 & 15) << 2;
                    float4* q = (float4*)&hs2[k1 * 64 + b41];
                    q[0] = make_float4(hv1.x, hv1.x, hv1.y, hv1.y);
                    q[1] = make_float4(hv1.z, hv1.z, hv1.w, hv1.w);
                }
            }
            __syncthreads();

            if (blk < HID / BK - 1) {          // prefetch next block
                const float4* hn = hsrc + (blk + 1) * (BK * BATCH / 4);
                hv0 = ldcg4(hn + tid);
                if (tid < 128) hv1 = ldcg4(hn + 384 + tid);
            }

            const int kg = g * 8;              // group's local k base
#pragma unroll
            for (int kk = 0; kk < 8; kk++) {
                const float* wrow = wsT + (size_t)(blk * BK + kg + kk) * WPITCH;
                ull wA = *(const ull*)(wrow + 2 * tx);
                ull wB = *(const ull*)(wrow + 24 + 2 * tx);
                const ulonglong2* hrow =
                    (const ulonglong2*)&hs2[(kg + kk) * 64 + b0];
                ulonglong2 h01 = hrow[0];
                ulonglong2 h23 = hrow[1];
                ulonglong2 h45 = hrow[2];
                ulonglong2 h67 = hrow[3];
                acc[0][0] = fma2(wA, h01.x, acc[0][0]);
                acc[1][0] = fma2(wB, h01.x, acc[1][0]);
                acc[0][1] = fma2(wA, h01.y, acc[0][1]);
                acc[1][1] = fma2(wB, h01.y, acc[1][1]);
                acc[0][2] = fma2(wA, h23.x, acc[0][2]);
                acc[1][2] = fma2(wB, h23.x, acc[1][2]);
                acc[0][3] = fma2(wA, h23.y, acc[0][3]);
                acc[1][3] = fma2(wB, h23.y, acc[1][3]);
                acc[0][4] = fma2(wA, h45.x, acc[0][4]);
                acc[1][4] = fma2(wB, h45.x, acc[1][4]);
                acc[0][5] = fma2(wA, h45.y, acc[0][5]);
                acc[1][5] = fma2(wB, h45.y, acc[1][5]);
                acc[0][6] = fma2(wA, h67.x, acc[0][6]);
                acc[1][6] = fma2(wB, h67.x, acc[1][6]);
                acc[0][7] = fma2(wA, h67.y, acc[0][7]);
                acc[1][7] = fma2(wB, h67.y, acc[1][7]);
            }
        }

        // ---- reduce 4 K-groups via tree over red buf (overlaid on hs2) ----
        __syncthreads();
        if (g == 1) red_write(red, r, acc);
        __syncthreads();
        if (g == 0) red_add(red, r, acc);
        __syncthreads();
        if (g == 3) red_write(red, r, acc);
        __syncthreads();
        if (g == 2) red_add(red, r, acc);
        __syncthreads();
        if (g == 2) red_write(red, r, acc);
        __syncthreads();
        if (g == 0) red_add(red, r, acc);
        __syncthreads();
        if (g == 0) {                // final gh[b][c], pitch 48
#pragma unroll
            for (int cp = 0; cp < 2; cp++) {
                int cb = cp ? (24 + 2*tx) : (2*tx);
#pragma unroll
                for (int bb = 0; bb < 8; bb++) {
                    float2 f = unpack2(acc[cp][bb]);
                    *(float2*)&ghf[(b0 + bb) * 48 + cb] = f;
                }
            }
        }
        __syncthreads();

        // ---- fused gate epilogue ----
#pragma unroll
        for (int e = 0; e < 3; e++) {
            int idx = tid + 384 * e;
            if (idx < 1024) {
                int b = idx >> 4, jj = idx & 15, j = jbase + jj;
                float gr = ghf[b * 48 + jj];
                float gz = ghf[b * 48 + 16 + jj];
                float gn = ghf[b * 48 + 32 + jj];
                float rg = 1.f / (1.f + expf(-(pgr[e] + gr + bsm[jj])));
                float zg = 1.f / (1.f + expf(-(pgz[e] + gz + bsm[16 + jj])));
                float ng = tanhf(pgn[e] + rg * (gn + bsm[32 + jj]));
                float h  = ng + zg * (php[e] - ng);
                h_out[(size_t)j * BATCH + b] = h;
                if (yout)
                    yout[((size_t)tt * BATCH + b) * 2048 + (size_t)d * HID + j] = h;
                if (t == T_STEPS - 1)
                    hn_out[(size_t)d * (BATCH*HID) + (size_t)b * HID + j] = h;
            }
        }

        // ---- grid barrier (all 128 CTAs co-resident) ----
        __syncthreads();
        if (tid == 0) {
            __threadfence();
            atomicAdd(&g_bar, 1u);
            unsigned target = 128u * (unsigned)(t + 1);
            unsigned v;
            do {
                asm volatile("ld.acquire.gpu.global.u32 %0, [%1];"
                             : "=r"(v) : "l"(&g_bar) : "memory");
            } while (v < target);
        }
        __syncthreads();
    }
}

// ---------------------------------------------------------------------------
// Host: per layer: init_layer + gemm_gx + gru_layer (persistent).
// ---------------------------------------------------------------------------
namespace {
struct EagerLoad {
    EagerLoad() {
        void* p;
        cudaGetSymbolAddress(&p, g_gx);
        cudaGetSymbolAddress(&p, g_bufA);
        cudaGetSymbolAddress(&p, g_bufB);
        cudaGetSymbolAddress(&p, g_hbuf);
        cudaGetSymbolAddress(&p, g_bar);
        cudaFuncSetAttribute(gru_layer,
                             cudaFuncAttributeMaxDynamicSharedMemorySize,
                             SM_TOTAL);
    }
} s_eager_load;
}

extern "C" void kernel_launch(void* const* d_in, const int* in_sizes, int n_in,
                              void* d_out, int out_size)
{
    const float* x    = (const float*)d_in[0];
    const float* h0   = (const float*)d_in[1];
    const float* w_ih = (const float*)d_in[2];
    const float* w_hh = (const float*)d_in[3];
    const float* b_ih = (const float*)d_in[4];
    const float* b_hh = (const float*)d_in[5];
    float* out = (float*)d_out;
    (void)in_sizes; (void)n_in; (void)out_size;

    float *gx, *bufA, *bufB, *hbuf;
    cudaGetSymbolAddress((void**)&gx,   g_gx);
    cudaGetSymbolAddress((void**)&bufA, g_bufA);
    cudaGetSymbolAddress((void**)&bufB, g_bufB);
    cudaGetSymbolAddress((void**)&hbuf, g_hbuf);

    dim3 ggrid(NW / 128, MW / 128);   // (48, 128)

    for (int l = 0; l < 3; l++) {
        const float* in = (l == 0) ? x : ((l == 1) ? bufA : bufB);
        float* yout     = (l == 0) ? bufA : ((l == 1) ? bufB : nullptr);

        init_layer<<<512, 256>>>(h0 + (size_t)l * 2 * BATCH * HID, hbuf);

        gemm_gx<<<ggrid, 256>>>(in, w_ih + (size_t)l * NW * KW,
                                b_ih + (size_t)l * NW, gx);

        gru_layer<<<128, LT_THREADS, SM_TOTAL>>>(
            gx,
            w_hh + (size_t)l * 2 * GATES * HID,
            b_hh + (size_t)l * NW,
            hbuf, yout,
            out + (size_t)l * 2 * BATCH * HID);
    }
}

// round 8
// speedup vs baseline: 1.5497x; 1.1269x over previous
#include <cuda_runtime.h>
#include <math.h>
#include <cstddef>

// ---------------------------------------------------------------------------
// 3-layer bidirectional GRU, fp32, FFMA2 (fma.rn.f32x2).
//   T=256, B=64, IN=2048 (=2H), H=1024, L=3, D=2
// Per layer: init_layer + gemm_gx + gru_layer (persistent, all 256 steps).
// R8 gru_layer: batch-paired FFMA2, non-duplicated h, w reg-dup via MOV,
//               8x8 microtile, 8-way K-split, BK=64.
// ---------------------------------------------------------------------------

#define T_STEPS 256
#define BATCH   64
#define HID     1024
#define GATES   3072
#define NW      6144
#define KW      2048
#define MW      16384

#define LT_THREADS 384
#define BK      64
#define WPITCH  52            // floats per k-row of wsT (mult of 4; 80B stagger)
#define HPITCH  68            // floats per k-row of hs  (mult of 4; 16B stagger)
#define GPITCH  52            // floats per b-row of ghf (mult of 4)

__device__ float g_gx  [(size_t)MW * NW];
__device__ float g_bufA[(size_t)T_STEPS * BATCH * 2048];
__device__ float g_bufB[(size_t)T_STEPS * BATCH * 2048];
__device__ float g_hbuf[2 * 2 * HID * BATCH];   // [dir][parity][j][b] transposed
__device__ unsigned g_bar;

typedef unsigned long long ull;

__device__ __forceinline__ ull fma2(ull a, ull b, ull c) {
    ull d;
    asm("fma.rn.f32x2 %0, %1, %2, %3;" : "=l"(d) : "l"(a), "l"(b), "l"(c));
    return d;
}
__device__ __forceinline__ ull dup2(float x) {
    ull d;
    asm("mov.b64 %0, {%1, %1};" : "=l"(d) : "f"(x));
    return d;
}
__device__ __forceinline__ float2 unpack2(ull v) {
    float2 f;
    asm("mov.b64 {%0, %1}, %2;" : "=f"(f.x), "=f"(f.y) : "l"(v));
    return f;
}
__device__ __forceinline__ float4 ldcg4(const float4* p) {
    float4 v;
    asm volatile("ld.global.cg.v4.f32 {%0,%1,%2,%3}, [%4];"
                 : "=f"(v.x), "=f"(v.y), "=f"(v.z), "=f"(v.w) : "l"(p));
    return v;
}
__device__ __forceinline__ float ldcg1(const float* p) {
    float v;
    asm volatile("ld.global.cg.f32 %0, [%1];" : "=f"(v) : "l"(p));
    return v;
}

// ---------------------------------------------------------------------------
// Kernel 0: per-layer init. Transpose h0[l] -> hbufT parity-1; zero g_bar.
// ---------------------------------------------------------------------------
__global__ __launch_bounds__(256) void init_layer(const float* __restrict__ h0_l,
                                                  float* __restrict__ hbuf)
{
    int idx = blockIdx.x * 256 + threadIdx.x;      // [0, 131072)
    if (idx == 0) g_bar = 0u;
    int d = idx >> 16;
    int r = idx & 65535;
    int j = r & (HID - 1);
    int b = r >> 10;
    hbuf[(size_t)(d * 2 + 1) * (HID * BATCH) + j * BATCH + b] =
        h0_l[(size_t)d * (BATCH * HID) + (size_t)b * HID + j];
}

// ---------------------------------------------------------------------------
// Kernel 1: gx GEMM (near FFMA2 roofline; unchanged).
// ---------------------------------------------------------------------------
__global__ __launch_bounds__(256) void gemm_gx(
    const float* __restrict__ A, const float* __restrict__ W,
    const float* __restrict__ bias, float* __restrict__ C)
{
    __shared__ __align__(16) float2 As2[16][128];
    __shared__ __align__(16) float  Bs [16][128];

    const int tid = threadIdx.x;
    const int tx  = tid & 15;
    const int ty  = tid >> 4;
    const int n0  = blockIdx.x * 128;
    const int m0  = blockIdx.y * 128;

    const int r0  = tid >> 2;
    const int kq4 = (tid & 3) * 4;

    const float* Ap0 = A + (size_t)(m0 + r0)      * KW + kq4;
    const float* Ap1 = A + (size_t)(m0 + r0 + 64) * KW + kq4;
    const float* Wp0 = W + (size_t)(n0 + r0)      * KW + kq4;
    const float* Wp1 = W + (size_t)(n0 + r0 + 64) * KW + kq4;

    ull acc[8][4];
#pragma unroll
    for (int m = 0; m < 8; m++)
#pragma unroll
        for (int q = 0; q < 4; q++) acc[m][q] = 0ULL;

    float4 va0 = *(const float4*)Ap0;
    float4 va1 = *(const float4*)Ap1;
    float4 vw0 = *(const float4*)Wp0;
    float4 vw1 = *(const float4*)Wp1;

    for (int k0 = 0; k0 < KW; k0 += 16) {
        __syncthreads();
        As2[kq4+0][r0]    = make_float2(va0.x, va0.x);
        As2[kq4+1][r0]    = make_float2(va0.y, va0.y);
        As2[kq4+2][r0]    = make_float2(va0.z, va0.z);
        As2[kq4+3][r0]    = make_float2(va0.w, va0.w);
        As2[kq4+0][r0+64] = make_float2(va1.x, va1.x);
        As2[kq4+1][r0+64] = make_float2(va1.y, va1.y);
        As2[kq4+2][r0+64] = make_float2(va1.z, va1.z);
        As2[kq4+3][r0+64] = make_float2(va1.w, va1.w);
        Bs[kq4+0][r0]     = vw0.x;
        Bs[kq4+1][r0]     = vw0.y;
        Bs[kq4+2][r0]     = vw0.z;
        Bs[kq4+3][r0]     = vw0.w;
        Bs[kq4+0][r0+64]  = vw1.x;
        Bs[kq4+1][r0+64]  = vw1.y;
        Bs[kq4+2][r0+64]  = vw1.z;
        Bs[kq4+3][r0+64]  = vw1.w;
        __syncthreads();

        if (k0 + 16 < KW) {
            va0 = *(const float4*)(Ap0 + k0 + 16);
            va1 = *(const float4*)(Ap1 + k0 + 16);
            vw0 = *(const float4*)(Wp0 + k0 + 16);
            vw1 = *(const float4*)(Wp1 + k0 + 16);
        }

#pragma unroll
        for (int k = 0; k < 16; k++) {
            ull ad[8];
#pragma unroll
            for (int m = 0; m < 8; m++)
                ad[m] = *(const ull*)&As2[k][ty*8 + m];
            ulonglong2 bA = *(const ulonglong2*)&Bs[k][tx*8];
            ulonglong2 bB = *(const ulonglong2*)&Bs[k][tx*8 + 4];
#pragma unroll
            for (int m = 0; m < 8; m++) {
                acc[m][0] = fma2(ad[m], bA.x, acc[m][0]);
                acc[m][1] = fma2(ad[m], bA.y, acc[m][1]);
                acc[m][2] = fma2(ad[m], bB.x, acc[m][2]);
                acc[m][3] = fma2(ad[m], bB.y, acc[m][3]);
            }
        }
    }

    float bias8[8];
#pragma unroll
    for (int c = 0; c < 8; c++) bias8[c] = bias[n0 + tx*8 + c];

#pragma unroll
    for (int m = 0; m < 8; m++) {
        float* Cp = C + (size_t)(m0 + ty*8 + m) * NW + n0 + tx*8;
        float o[8];
#pragma unroll
        for (int q = 0; q < 4; q++) {
            float2 f = unpack2(acc[m][q]);
            o[2*q]   = f.x + bias8[2*q];
            o[2*q+1] = f.y + bias8[2*q+1];
        }
        *(float4*)(Cp)     = make_float4(o[0], o[1], o[2], o[3]);
        *(float4*)(Cp + 4) = make_float4(o[4], o[5], o[6], o[7]);
    }
}

// ---------------------------------------------------------------------------
// Kernel 2 (R8): persistent per-layer GRU. 128 CTAs: d=bx>>6, jbase=(bx&63)*16.
// SMEM: wsT[1024][52] whh slice ([k][c]); hs[64][68] non-dup h tile
// (overlaid by ghf[64][52]); bsm[48].
// Microtile: 8 cols x 8 batches (batch-paired FFMA2, w reg-dup'd).
// K-split 8 ways (48 positions x 8 groups), sequential 8-round reduction.
// ---------------------------------------------------------------------------
#define SM_WS_BYTES  (HID * WPITCH * 4)          // 212992
#define SM_HS_BYTES  (BK * HPITCH * 4)           // 17408
#define SM_TOTAL     (SM_WS_BYTES + SM_HS_BYTES + 256)   // 230656

__global__ __launch_bounds__(LT_THREADS, 1) void gru_layer(
    const float* __restrict__ gx, const float* __restrict__ whh_l,
    const float* __restrict__ bhh_l, float* __restrict__ hbuf,
    float* __restrict__ yout, float* __restrict__ hn_out)
{
    extern __shared__ char smraw[];
    float* wsT = (float*)smraw;                          // [1024][WPITCH]
    float* hs  = (float*)(smraw + SM_WS_BYTES);          // [64][HPITCH]
    float* ghf = hs;                                     // overlay [64][GPITCH]
    float* bsm = (float*)(smraw + SM_WS_BYTES + SM_HS_BYTES);

    const int tid = threadIdx.x;
    const int d     = blockIdx.x >> 6;
    const int jbase = (blockIdx.x & 63) << 4;
    const int g   = tid / 48;         // K-split group 0..7
    const int pos = tid % 48;
    const int c0  = (pos % 6) * 8;    // 8 cols
    const int b0  = (pos / 6) * 8;    // 8 batches (4 pairs)

    const float* whh = whh_l + (size_t)d * GATES * HID;
    const float* bhh = bhh_l + d * GATES;

    // ---- load whh slice into wsT ([k][c]) once per layer ----
#pragma unroll 4
    for (int it = 0; it < 32; it++) {
        int f4i = tid + it * 384;            // 0..12287
        int c   = f4i >> 8;                  // 0..47
        int kq  = (f4i & 255) << 2;
        int grow = ((c >> 4) << 10) + jbase + (c & 15);
        float4 v = *(const float4*)(whh + (size_t)grow * HID + kq);
        wsT[(kq + 0) * WPITCH + c] = v.x;
        wsT[(kq + 1) * WPITCH + c] = v.y;
        wsT[(kq + 2) * WPITCH + c] = v.z;
        wsT[(kq + 3) * WPITCH + c] = v.w;
    }
    if (tid < 48)
        bsm[tid] = bhh[((tid >> 4) << 10) + jbase + (tid & 15)];
    __syncthreads();

    for (int t = 0; t < T_STEPS; t++) {
        const float* h_in  = hbuf + (size_t)(d*2 + ((t&1)^1)) * (HID*BATCH);
        float*       h_out = hbuf + (size_t)(d*2 + (t&1))     * (HID*BATCH);
        const int tt = d ? (T_STEPS - 1 - t) : t;
        const float* gxp = gx + (size_t)tt * BATCH * NW + (size_t)d * GATES;

        // prefetch epilogue operands (latency hidden under mainloop)
        float pgr[3], pgz[3], pgn[3], php[3];
#pragma unroll
        for (int e = 0; e < 3; e++) {
            int idx = tid + 384 * e;
            pgr[e] = pgz[e] = pgn[e] = php[e] = 0.f;
            if (idx < 1024) {
                int b = idx >> 4, jj = idx & 15, j = jbase + jj;
                const float* gxb = gxp + (size_t)b * NW;
                pgr[e] = __ldg(gxb + j);
                pgz[e] = __ldg(gxb + HID + j);
                pgn[e] = __ldg(gxb + 2*HID + j);
                php[e] = ldcg1(h_in + (size_t)j * BATCH + b);
            }
        }

        ull acc[8][4];
#pragma unroll
        for (int cc = 0; cc < 8; cc++)
#pragma unroll
            for (int bp = 0; bp < 4; bp++) acc[cc][bp] = 0ULL;

        // initial staging fetch (blk 0): 1024 float4 per block of 64 k
        const float4* hsrc = (const float4*)h_in;     // [j][b]
        float4 hv0 = ldcg4(hsrc + tid);
        float4 hv1 = ldcg4(hsrc + 384 + tid);
        float4 hv2 = make_float4(0.f,0.f,0.f,0.f);
        if (tid < 256) hv2 = ldcg4(hsrc + 768 + tid);

        for (int blk = 0; blk < HID / BK; blk++) {     // 16 blocks
            __syncthreads();
            {   // store non-duplicated h tile, pitch HPITCH
                int i0 = tid;
                *(float4*)&hs[(i0 >> 4) * HPITCH + ((i0 & 15) << 2)] = hv0;
                int i1 = tid + 384;
                *(float4*)&hs[(i1 >> 4) * HPITCH + ((i1 & 15) << 2)] = hv1;
                if (tid < 256) {
                    int i2 = tid + 768;
                    *(float4*)&hs[(i2 >> 4) * HPITCH + ((i2 & 15) << 2)] = hv2;
                }
            }
            __syncthreads();

            if (blk < HID / BK - 1) {          // prefetch next block
                const float4* hn = hsrc + (blk + 1) * (BK * BATCH / 4);
                hv0 = ldcg4(hn + tid);
                hv1 = ldcg4(hn + 384 + tid);
                if (tid < 256) hv2 = ldcg4(hn + 768 + tid);
            }

            const int kbase = g * 8;           // group's local k slice
#pragma unroll
            for (int kk = 0; kk < 8; kk++) {
                const int krow = kbase + kk;
                const float* wr = wsT + (size_t)(blk * BK + krow) * WPITCH + c0;
                float4 wa = *(const float4*)wr;
                float4 wb = *(const float4*)(wr + 4);
                ull ww0 = dup2(wa.x), ww1 = dup2(wa.y);
                ull ww2 = dup2(wa.z), ww3 = dup2(wa.w);
                ull ww4 = dup2(wb.x), ww5 = dup2(wb.y);
                ull ww6 = dup2(wb.z), ww7 = dup2(wb.w);
                const float* hr = hs + krow * HPITCH + b0;
                ulonglong2 hA = *(const ulonglong2*)hr;        // pairs 0,1
                ulonglong2 hB = *(const ulonglong2*)(hr + 4);  // pairs 2,3
                acc[0][0] = fma2(hA.x, ww0, acc[0][0]);
                acc[1][0] = fma2(hA.x, ww1, acc[1][0]);
                acc[2][0] = fma2(hA.x, ww2, acc[2][0]);
                acc[3][0] = fma2(hA.x, ww3, acc[3][0]);
                acc[4][0] = fma2(hA.x, ww4, acc[4][0]);
                acc[5][0] = fma2(hA.x, ww5, acc[5][0]);
                acc[6][0] = fma2(hA.x, ww6, acc[6][0]);
                acc[7][0] = fma2(hA.x, ww7, acc[7][0]);
                acc[0][1] = fma2(hA.y, ww0, acc[0][1]);
                acc[1][1] = fma2(hA.y, ww1, acc[1][1]);
                acc[2][1] = fma2(hA.y, ww2, acc[2][1]);
                acc[3][1] = fma2(hA.y, ww3, acc[3][1]);
                acc[4][1] = fma2(hA.y, ww4, acc[4][1]);
                acc[5][1] = fma2(hA.y, ww5, acc[5][1]);
                acc[6][1] = fma2(hA.y, ww6, acc[6][1]);
                acc[7][1] = fma2(hA.y, ww7, acc[7][1]);
                acc[0][2] = fma2(hB.x, ww0, acc[0][2]);
                acc[1][2] = fma2(hB.x, ww1, acc[1][2]);
                acc[2][2] = fma2(hB.x, ww2, acc[2][2]);
                acc[3][2] = fma2(hB.x, ww3, acc[3][2]);
                acc[4][2] = fma2(hB.x, ww4, acc[4][2]);
                acc[5][2] = fma2(hB.x, ww5, acc[5][2]);
                acc[6][2] = fma2(hB.x, ww6, acc[6][2]);
                acc[7][2] = fma2(hB.x, ww7, acc[7][2]);
                acc[0][3] = fma2(hB.y, ww0, acc[0][3]);
                acc[1][3] = fma2(hB.y, ww1, acc[1][3]);
                acc[2][3] = fma2(hB.y, ww2, acc[2][3]);
                acc[3][3] = fma2(hB.y, ww3, acc[3][3]);
                acc[4][3] = fma2(hB.y, ww4, acc[4][3]);
                acc[5][3] = fma2(hB.y, ww5, acc[5][3]);
                acc[6][3] = fma2(hB.y, ww6, acc[6][3]);
                acc[7][3] = fma2(hB.y, ww7, acc[7][3]);
            }
        }

        // ---- 8-round sequential K-group reduction into ghf (overlay on hs) --
        __syncthreads();          // hs dead from here
#pragma unroll 1
        for (int gr = 0; gr < 8; gr++) {
            if (g == gr) {
#pragma unroll
                for (int bb = 0; bb < 8; bb++) {
                    float o[8];
#pragma unroll
                    for (int cc = 0; cc < 8; cc++) {
                        float2 f = unpack2(acc[cc][bb >> 1]);
                        o[cc] = (bb & 1) ? f.y : f.x;
                    }
                    float* gp = ghf + (b0 + bb) * GPITCH + c0;
                    if (gr == 0) {
                        *(float4*)gp       = make_float4(o[0], o[1], o[2], o[3]);
                        *(float4*)(gp + 4) = make_float4(o[4], o[5], o[6], o[7]);
                    } else {
                        float4 p0 = *(float4*)gp;
                        float4 p1 = *(float4*)(gp + 4);
                        *(float4*)gp = make_float4(p0.x + o[0], p0.y + o[1],
                                                   p0.z + o[2], p0.w + o[3]);
                        *(float4*)(gp + 4) = make_float4(p1.x + o[4], p1.y + o[5],
                                                         p1.z + o[6], p1.w + o[7]);
                    }
                }
            }
            __syncthreads();
        }

        // ---- fused gate epilogue ----
#pragma unroll
        for (int e = 0; e < 3; e++) {
            int idx = tid + 384 * e;
            if (idx < 1024) {
                int b = idx >> 4, jj = idx & 15, j = jbase + jj;
                float gr = ghf[b * GPITCH + jj];
                float gz = ghf[b * GPITCH + 16 + jj];
                float gn = ghf[b * GPITCH + 32 + jj];
                float rg = 1.f / (1.f + expf(-(pgr[e] + gr + bsm[jj])));
                float zg = 1.f / (1.f + expf(-(pgz[e] + gz + bsm[16 + jj])));
                float ng = tanhf(pgn[e] + rg * (gn + bsm[32 + jj]));
                float h  = ng + zg * (php[e] - ng);
                h_out[(size_t)j * BATCH + b] = h;
                if (yout)
                    yout[((size_t)tt * BATCH + b) * 2048 + (size_t)d * HID + j] = h;
                if (t == T_STEPS - 1)
                    hn_out[(size_t)d * (BATCH*HID) + (size_t)b * HID + j] = h;
            }
        }

        // ---- grid barrier (128 CTAs co-resident, 1 wave) ----
        __syncthreads();
        if (tid == 0) {
            __threadfence();
            atomicAdd(&g_bar, 1u);
            unsigned target = 128u * (unsigned)(t + 1);
            unsigned v;
            do {
                asm volatile("ld.acquire.gpu.global.u32 %0, [%1];"
                             : "=r"(v) : "l"(&g_bar) : "memory");
            } while (v < target);
        }
        __syncthreads();
    }
}

// ---------------------------------------------------------------------------
// Host
// ---------------------------------------------------------------------------
namespace {
struct EagerLoad {
    EagerLoad() {
        void* p;
        cudaGetSymbolAddress(&p, g_gx);
        cudaGetSymbolAddress(&p, g_bufA);
        cudaGetSymbolAddress(&p, g_bufB);
        cudaGetSymbolAddress(&p, g_hbuf);
        cudaGetSymbolAddress(&p, g_bar);
        cudaFuncSetAttribute(gru_layer,
                             cudaFuncAttributeMaxDynamicSharedMemorySize,
                             SM_TOTAL);
    }
} s_eager_load;
}

extern "C" void kernel_launch(void* const* d_in, const int* in_sizes, int n_in,
                              void* d_out, int out_size)
{
    const float* x    = (const float*)d_in[0];
    const float* h0   = (const float*)d_in[1];
    const float* w_ih = (const float*)d_in[2];
    const float* w_hh = (const float*)d_in[3];
    const float* b_ih = (const float*)d_in[4];
    const float* b_hh = (const float*)d_in[5];
    float* out = (float*)d_out;
    (void)in_sizes; (void)n_in; (void)out_size;

    float *gx, *bufA, *bufB, *hbuf;
    cudaGetSymbolAddress((void**)&gx,   g_gx);
    cudaGetSymbolAddress((void**)&bufA, g_bufA);
    cudaGetSymbolAddress((void**)&bufB, g_bufB);
    cudaGetSymbolAddress((void**)&hbuf, g_hbuf);

    dim3 ggrid(NW / 128, MW / 128);   // (48, 128)

    for (int l = 0; l < 3; l++) {
        const float* in = (l == 0) ? x : ((l == 1) ? bufA : bufB);
        float* yout     = (l == 0) ? bufA : ((l == 1) ? bufB : nullptr);

        init_layer<<<512, 256>>>(h0 + (size_t)l * 2 * BATCH * HID, hbuf);

        gemm_gx<<<ggrid, 256>>>(in, w_ih + (size_t)l * NW * KW,
                                b_ih + (size_t)l * NW, gx);

        gru_layer<<<128, LT_THREADS, SM_TOTAL>>>(
            gx,
            w_hh + (size_t)l * 2 * GATES * HID,
            b_hh + (size_t)l * NW,
            hbuf, yout,
            out + (size_t)l * 2 * BATCH * HID);
    }
}

// round 9
// speedup vs baseline: 3.1902x; 2.0586x over previous
#include <cuda_runtime.h>
#include <math.h>
#include <cstddef>
#include <cstdint>

// ---------------------------------------------------------------------------
// 3-layer bidirectional GRU.  T=256, B=64, IN=2048 (=2H), H=1024, L=3, D=2
// Per layer: init_layer + gemm_gx (tf32 mma.sync) + gru_layer (persistent).
// R9: gemm uses m16n8k8 tf32 tensor-core MMA; gru mainloop de-spilled
//     (acc[4][4], 4-way K-split), last-step barrier skipped.
// ---------------------------------------------------------------------------

#define T_STEPS 256
#define BATCH   64
#define HID     1024
#define GATES   3072
#define NW      6144
#define KW      2048
#define MW      16384

#define LT_THREADS 384
#define BK      64
#define WPITCH  52
#define HPITCH  68
#define GPITCH  52

__device__ float g_gx  [(size_t)MW * NW];
__device__ float g_bufA[(size_t)T_STEPS * BATCH * 2048];
__device__ float g_bufB[(size_t)T_STEPS * BATCH * 2048];
__device__ float g_hbuf[2 * 2 * HID * BATCH];   // [dir][parity][j][b] transposed
__device__ unsigned g_bar;

typedef unsigned long long ull;

__device__ __forceinline__ ull fma2(ull a, ull b, ull c) {
    ull d;
    asm("fma.rn.f32x2 %0, %1, %2, %3;" : "=l"(d) : "l"(a), "l"(b), "l"(c));
    return d;
}
__device__ __forceinline__ ull dup2(float x) {
    ull d;
    asm("mov.b64 %0, {%1, %1};" : "=l"(d) : "f"(x));
    return d;
}
__device__ __forceinline__ float2 unpack2(ull v) {
    float2 f;
    asm("mov.b64 {%0, %1}, %2;" : "=f"(f.x), "=f"(f.y) : "l"(v));
    return f;
}
__device__ __forceinline__ float4 ldcg4(const float4* p) {
    float4 v;
    asm volatile("ld.global.cg.v4.f32 {%0,%1,%2,%3}, [%4];"
                 : "=f"(v.x), "=f"(v.y), "=f"(v.z), "=f"(v.w) : "l"(p));
    return v;
}
__device__ __forceinline__ float ldcg1(const float* p) {
    float v;
    asm volatile("ld.global.cg.f32 %0, [%1];" : "=f"(v) : "l"(p));
    return v;
}
// tf32 warp MMA: D(16x8) += A(16x8,row) * B(8x8,col). fp32 bits fed as tf32.
__device__ __forceinline__ void mma_tf32(float d[4], const uint32_t a[4],
                                         const uint32_t b[2]) {
    asm("mma.sync.aligned.m16n8k8.row.col.f32.tf32.tf32.f32 "
        "{%0,%1,%2,%3}, {%4,%5,%6,%7}, {%8,%9}, {%0,%1,%2,%3};"
        : "+f"(d[0]), "+f"(d[1]), "+f"(d[2]), "+f"(d[3])
        : "r"(a[0]), "r"(a[1]), "r"(a[2]), "r"(a[3]), "r"(b[0]), "r"(b[1]));
}

// ---------------------------------------------------------------------------
// Kernel 0: per-layer init. Transpose h0[l] -> hbufT parity-1; zero g_bar.
// ---------------------------------------------------------------------------
__global__ __launch_bounds__(256) void init_layer(const float* __restrict__ h0_l,
                                                  float* __restrict__ hbuf)
{
    int idx = blockIdx.x * 256 + threadIdx.x;      // [0, 131072)
    if (idx == 0) g_bar = 0u;
    int d = idx >> 16;
    int r = idx & 65535;
    int j = r & (HID - 1);
    int b = r >> 10;
    hbuf[(size_t)(d * 2 + 1) * (HID * BATCH) + j * BATCH + b] =
        h0_l[(size_t)d * (BATCH * HID) + (size_t)b * HID + j];
}

// ---------------------------------------------------------------------------
// Kernel 1 (R9): gx GEMM with tf32 mma.sync.
//   C[m,n] = sum_k A[m,k]*W[n,k] + bias[n]; both operands K-contiguous
//   => row.col MMA directly. CTA 128x128xBK32, 256 thr = 8 warps (2m x 4n),
//   warp tile 64x32, per-warp 4x4 frags of m16n8k8. SMEM pitch 36 floats
//   makes all fragment gathers bank-conflict-free.
// ---------------------------------------------------------------------------
#define GP 36
__global__ __launch_bounds__(256) void gemm_gx(
    const float* __restrict__ A, const float* __restrict__ W,
    const float* __restrict__ bias, float* __restrict__ C)
{
    __shared__ __align__(16) float As[128][GP];
    __shared__ __align__(16) float Ws[128][GP];

    const int tid  = threadIdx.x;
    const int lane = tid & 31;
    const int wid  = tid >> 5;
    const int wm   = wid & 1;          // 2 warps in m
    const int wn   = wid >> 1;         // 4 warps in n
    const int g    = lane >> 2;        // mma group id 0..7
    const int c    = lane & 3;         // mma thread-in-group 0..3
    const int n0   = blockIdx.x * 128;
    const int m0   = blockIdx.y * 128;

    // staging: 1024 float4 per operand tile / 256 thr = 4 each
    const int srow = tid >> 3;          // 0..31
    const int skq  = (tid & 7) * 4;     // 0..28

    const float* Ap[4];
    const float* Wp[4];
#pragma unroll
    for (int i = 0; i < 4; i++) {
        Ap[i] = A + (size_t)(m0 + srow + 32 * i) * KW + skq;
        Wp[i] = W + (size_t)(n0 + srow + 32 * i) * KW + skq;
    }

    float acc[4][4][4];
#pragma unroll
    for (int mi = 0; mi < 4; mi++)
#pragma unroll
        for (int nj = 0; nj < 4; nj++)
#pragma unroll
            for (int q = 0; q < 4; q++) acc[mi][nj][q] = 0.f;

    float4 va[4], vw[4];
#pragma unroll
    for (int i = 0; i < 4; i++) { va[i] = *(const float4*)Ap[i];
                                  vw[i] = *(const float4*)Wp[i]; }

    const int mbase = wm * 64;
    const int nbase = wn * 32;

    for (int k0 = 0; k0 < KW; k0 += 32) {
        __syncthreads();
#pragma unroll
        for (int i = 0; i < 4; i++) {
            *(float4*)&As[srow + 32 * i][skq] = va[i];
            *(float4*)&Ws[srow + 32 * i][skq] = vw[i];
        }
        __syncthreads();

        if (k0 + 32 < KW) {
#pragma unroll
            for (int i = 0; i < 4; i++) {
                va[i] = *(const float4*)(Ap[i] + k0 + 32);
                vw[i] = *(const float4*)(Wp[i] + k0 + 32);
            }
        }

#pragma unroll
        for (int ks = 0; ks < 4; ks++) {
            const int kb = ks * 8;
            uint32_t a[4][4], b[4][2];
#pragma unroll
            for (int mi = 0; mi < 4; mi++) {
                const int rb = mbase + mi * 16;
                a[mi][0] = __float_as_uint(As[rb + g    ][kb + c    ]);
                a[mi][1] = __float_as_uint(As[rb + g + 8][kb + c    ]);
                a[mi][2] = __float_as_uint(As[rb + g    ][kb + c + 4]);
                a[mi][3] = __float_as_uint(As[rb + g + 8][kb + c + 4]);
            }
#pragma unroll
            for (int nj = 0; nj < 4; nj++) {
                const int cb = nbase + nj * 8;
                b[nj][0] = __float_as_uint(Ws[cb + g][kb + c    ]);
                b[nj][1] = __float_as_uint(Ws[cb + g][kb + c + 4]);
            }
#pragma unroll
            for (int mi = 0; mi < 4; mi++)
#pragma unroll
                for (int nj = 0; nj < 4; nj++)
                    mma_tf32(acc[mi][nj], a[mi], b[nj]);
        }
    }

    // epilogue: per (mi,nj): rows mbase+mi*16+g(+8), cols nbase+nj*8+2c(,+1)
#pragma unroll
    for (int nj = 0; nj < 4; nj++) {
        const int col = n0 + nbase + nj * 8 + 2 * c;
        const float b0 = bias[col];
        const float b1 = bias[col + 1];
#pragma unroll
        for (int mi = 0; mi < 4; mi++) {
            const int row = m0 + mbase + mi * 16 + g;
            float* p0 = C + (size_t)row * NW + col;
            float* p1 = C + (size_t)(row + 8) * NW + col;
            *(float2*)p0 = make_float2(acc[mi][nj][0] + b0, acc[mi][nj][1] + b1);
            *(float2*)p1 = make_float2(acc[mi][nj][2] + b0, acc[mi][nj][3] + b1);
        }
    }
}

// ---------------------------------------------------------------------------
// Kernel 2 (R9): persistent per-layer GRU. 128 CTAs: d=bx>>6, jbase=(bx&63)*16.
// SMEM: wsT[1024][52] resident whh slice ([k][c]); hs[64][68] h tile
// (overlaid by ghf[64][52]); bsm[48].
// Microtile: 4 cols x 8 batches, batch-paired FFMA2, w reg-dup (acc=32 regs,
// no spill). K-split 4 ways (96 thr = 12 cpos x 8 bpos), 4-round reduction.
// ---------------------------------------------------------------------------
#define SM_WS_BYTES  (HID * WPITCH * 4)          // 212992
#define SM_HS_BYTES  (BK * HPITCH * 4)           // 17408
#define SM_TOTAL     (SM_WS_BYTES + SM_HS_BYTES + 256)   // 230656

__global__ __launch_bounds__(LT_THREADS, 1) void gru_layer(
    const float* __restrict__ gx, const float* __restrict__ whh_l,
    const float* __restrict__ bhh_l, float* __restrict__ hbuf,
    float* __restrict__ yout, float* __restrict__ hn_out)
{
    extern __shared__ char smraw[];
    float* wsT = (float*)smraw;                          // [1024][WPITCH]
    float* hs  = (float*)(smraw + SM_WS_BYTES);          // [64][HPITCH]
    float* ghf = hs;                                     // overlay [64][GPITCH]
    float* bsm = (float*)(smraw + SM_WS_BYTES + SM_HS_BYTES);

    const int tid = threadIdx.x;
    const int d     = blockIdx.x >> 6;
    const int jbase = (blockIdx.x & 63) << 4;
    const int g    = tid / 96;        // K-split group 0..3
    const int r    = tid - g * 96;
    const int c0   = (r % 12) * 4;    // 4 cols
    const int b0   = (r / 12) * 8;    // 8 batches (4 pairs)

    const float* whh = whh_l + (size_t)d * GATES * HID;
    const float* bhh = bhh_l + d * GATES;

    // ---- load whh slice into wsT ([k][c]) once per layer ----
#pragma unroll 4
    for (int it = 0; it < 32; it++) {
        int f4i = tid + it * 384;            // 0..12287
        int cc  = f4i >> 8;                  // 0..47
        int kq  = (f4i & 255) << 2;
        int grow = ((cc >> 4) << 10) + jbase + (cc & 15);
        float4 v = *(const float4*)(whh + (size_t)grow * HID + kq);
        wsT[(kq + 0) * WPITCH + cc] = v.x;
        wsT[(kq + 1) * WPITCH + cc] = v.y;
        wsT[(kq + 2) * WPITCH + cc] = v.z;
        wsT[(kq + 3) * WPITCH + cc] = v.w;
    }
    if (tid < 48)
        bsm[tid] = bhh[((tid >> 4) << 10) + jbase + (tid & 15)];
    __syncthreads();

    for (int t = 0; t < T_STEPS; t++) {
        const float* h_in  = hbuf + (size_t)(d*2 + ((t&1)^1)) * (HID*BATCH);
        float*       h_out = hbuf + (size_t)(d*2 + (t&1))     * (HID*BATCH);
        const int tt = d ? (T_STEPS - 1 - t) : t;
        const float* gxp = gx + (size_t)tt * BATCH * NW + (size_t)d * GATES;

        // prefetch epilogue operands (latency hidden under mainloop)
        float pgr[3], pgz[3], pgn[3], php[3];
#pragma unroll
        for (int e = 0; e < 3; e++) {
            int idx = tid + 384 * e;
            pgr[e] = pgz[e] = pgn[e] = php[e] = 0.f;
            if (idx < 1024) {
                int b = idx >> 4, jj = idx & 15, j = jbase + jj;
                const float* gxb = gxp + (size_t)b * NW;
                pgr[e] = __ldg(gxb + j);
                pgz[e] = __ldg(gxb + HID + j);
                pgn[e] = __ldg(gxb + 2*HID + j);
                php[e] = ldcg1(h_in + (size_t)j * BATCH + b);
            }
        }

        ull acc[4][4];
#pragma unroll
        for (int cc = 0; cc < 4; cc++)
#pragma unroll
            for (int bp = 0; bp < 4; bp++) acc[cc][bp] = 0ULL;

        // initial staging fetch (blk 0): 1024 float4 per 64-k block
        const float4* hsrc = (const float4*)h_in;     // [j][b]
        float4 hv0 = ldcg4(hsrc + tid);
        float4 hv1 = ldcg4(hsrc + 384 + tid);
        float4 hv2 = make_float4(0.f,0.f,0.f,0.f);
        if (tid < 256) hv2 = ldcg4(hsrc + 768 + tid);

        for (int blk = 0; blk < HID / BK; blk++) {     // 16 blocks
            __syncthreads();
            {   // store h tile, pitch HPITCH
                int i0 = tid;
                *(float4*)&hs[(i0 >> 4) * HPITCH + ((i0 & 15) << 2)] = hv0;
                int i1 = tid + 384;
                *(float4*)&hs[(i1 >> 4) * HPITCH + ((i1 & 15) << 2)] = hv1;
                if (tid < 256) {
                    int i2 = tid + 768;
                    *(float4*)&hs[(i2 >> 4) * HPITCH + ((i2 & 15) << 2)] = hv2;
                }
            }
            __syncthreads();

            if (blk < HID / BK - 1) {          // prefetch next block
                const float4* hn = hsrc + (blk + 1) * (BK * BATCH / 4);
                hv0 = ldcg4(hn + tid);
                hv1 = ldcg4(hn + 384 + tid);
                if (tid < 256) hv2 = ldcg4(hn + 768 + tid);
            }

            const int kbase = g * 16;          // group's 16-k slice
#pragma unroll
            for (int kk = 0; kk < 16; kk++) {
                const int krow = kbase + kk;
                const float4 wv =
                    *(const float4*)(wsT + (size_t)(blk * BK + krow) * WPITCH + c0);
                ull ww0 = dup2(wv.x), ww1 = dup2(wv.y);
                ull ww2 = dup2(wv.z), ww3 = dup2(wv.w);
                const float* hr = hs + krow * HPITCH + b0;
                ulonglong2 hA = *(const ulonglong2*)hr;        // pairs 0,1
                ulonglong2 hB = *(const ulonglong2*)(hr + 4);  // pairs 2,3
                acc[0][0] = fma2(hA.x, ww0, acc[0][0]);
                acc[1][0] = fma2(hA.x, ww1, acc[1][0]);
                acc[2][0] = fma2(hA.x, ww2, acc[2][0]);
                acc[3][0] = fma2(hA.x, ww3, acc[3][0]);
                acc[0][1] = fma2(hA.y, ww0, acc[0][1]);
                acc[1][1] = fma2(hA.y, ww1, acc[1][1]);
                acc[2][1] = fma2(hA.y, ww2, acc[2][1]);
                acc[3][1] = fma2(hA.y, ww3, acc[3][1]);
                acc[0][2] = fma2(hB.x, ww0, acc[0][2]);
                acc[1][2] = fma2(hB.x, ww1, acc[1][2]);
                acc[2][2] = fma2(hB.x, ww2, acc[2][2]);
                acc[3][2] = fma2(hB.x, ww3, acc[3][2]);
                acc[0][3] = fma2(hB.y, ww0, acc[0][3]);
                acc[1][3] = fma2(hB.y, ww1, acc[1][3]);
                acc[2][3] = fma2(hB.y, ww2, acc[2][3]);
                acc[3][3] = fma2(hB.y, ww3, acc[3][3]);
            }
        }

        // ---- 4-round sequential K-group reduction into ghf (overlay on hs) --
        __syncthreads();          // hs dead from here
#pragma unroll 1
        for (int gr = 0; gr < 4; gr++) {
            if (g == gr) {
#pragma unroll
                for (int bb = 0; bb < 8; bb++) {
                    float o[4];
#pragma unroll
                    for (int cc = 0; cc < 4; cc++) {
                        float2 f = unpack2(acc[cc][bb >> 1]);
                        o[cc] = (bb & 1) ? f.y : f.x;
                    }
                    float* gp = ghf + (b0 + bb) * GPITCH + c0;
                    if (gr == 0) {
                        *(float4*)gp = make_float4(o[0], o[1], o[2], o[3]);
                    } else {
                        float4 p = *(float4*)gp;
                        *(float4*)gp = make_float4(p.x + o[0], p.y + o[1],
                                                   p.z + o[2], p.w + o[3]);
                    }
                }
            }
            __syncthreads();
        }

        // ---- fused gate epilogue ----
#pragma unroll
        for (int e = 0; e < 3; e++) {
            int idx = tid + 384 * e;
            if (idx < 1024) {
                int b = idx >> 4, jj = idx & 15, j = jbase + jj;
                float gr = ghf[b * GPITCH + jj];
                float gz = ghf[b * GPITCH + 16 + jj];
                float gn = ghf[b * GPITCH + 32 + jj];
                float rg = 1.f / (1.f + expf(-(pgr[e] + gr + bsm[jj])));
                float zg = 1.f / (1.f + expf(-(pgz[e] + gz + bsm[16 + jj])));
                float ng = tanhf(pgn[e] + rg * (gn + bsm[32 + jj]));
                float h  = ng + zg * (php[e] - ng);
                h_out[(size_t)j * BATCH + b] = h;
                if (yout)
                    yout[((size_t)tt * BATCH + b) * 2048 + (size_t)d * HID + j] = h;
                if (t == T_STEPS - 1)
                    hn_out[(size_t)d * (BATCH*HID) + (size_t)b * HID + j] = h;
            }
        }

        // ---- grid barrier (128 CTAs co-resident; skip after last step) ----
        if (t < T_STEPS - 1) {
            __syncthreads();
            if (tid == 0) {
                __threadfence();
                atomicAdd(&g_bar, 1u);
                unsigned target = 128u * (unsigned)(t + 1);
                unsigned v;
                do {
                    asm volatile("ld.acquire.gpu.global.u32 %0, [%1];"
                                 : "=r"(v) : "l"(&g_bar) : "memory");
                } while (v < target);
            }
            __syncthreads();
        }
    }
}

// ---------------------------------------------------------------------------
// Host
// ---------------------------------------------------------------------------
namespace {
struct EagerLoad {
    EagerLoad() {
        void* p;
        cudaGetSymbolAddress(&p, g_gx);
        cudaGetSymbolAddress(&p, g_bufA);
        cudaGetSymbolAddress(&p, g_bufB);
        cudaGetSymbolAddress(&p, g_hbuf);
        cudaGetSymbolAddress(&p, g_bar);
        cudaFuncSetAttribute(gru_layer,
                             cudaFuncAttributeMaxDynamicSharedMemorySize,
                             SM_TOTAL);
    }
} s_eager_load;
}

extern "C" void kernel_launch(void* const* d_in, const int* in_sizes, int n_in,
                              void* d_out, int out_size)
{
    const float* x    = (const float*)d_in[0];
    const float* h0   = (const float*)d_in[1];
    const float* w_ih = (const float*)d_in[2];
    const float* w_hh = (const float*)d_in[3];
    const float* b_ih = (const float*)d_in[4];
    const float* b_hh = (const float*)d_in[5];
    float* out = (float*)d_out;
    (void)in_sizes; (void)n_in; (void)out_size;

    float *gx, *bufA, *bufB, *hbuf;
    cudaGetSymbolAddress((void**)&gx,   g_gx);
    cudaGetSymbolAddress((void**)&bufA, g_bufA);
    cudaGetSymbolAddress((void**)&bufB, g_bufB);
    cudaGetSymbolAddress((void**)&hbuf, g_hbuf);

    dim3 ggrid(NW / 128, MW / 128);   // (48, 128)

    for (int l = 0; l < 3; l++) {
        const float* in = (l == 0) ? x : ((l == 1) ? bufA : bufB);
        float* yout     = (l == 0) ? bufA : ((l == 1) ? bufB : nullptr);

        init_layer<<<512, 256>>>(h0 + (size_t)l * 2 * BATCH * HID, hbuf);

        gemm_gx<<<ggrid, 256>>>(in, w_ih + (size_t)l * NW * KW,
                                b_ih + (size_t)l * NW, gx);

        gru_layer<<<128, LT_THREADS, SM_TOTAL>>>(
            gx,
            w_hh + (size_t)l * 2 * GATES * HID,
            b_hh + (size_t)l * NW,
            hbuf, yout,
            out + (size_t)l * 2 * BATCH * HID);
    }
}